// round 9
// baseline (speedup 1.0000x reference)
#include <cuda_runtime.h>
#include <cuda_bf16.h>
#include <math.h>
#include <stdint.h>

// ---------------- problem constants ----------------
#define BB   8
#define HH   96
#define WW   96
#define CC   128
#define TT   (BB*HH*WW)      // 73728 tokens
#define NWIN 144             // 12*12 windows per image
#define WTOT (BB*NWIN)       // 1152 windows
#define NTOK 64              // tokens per window

// ---------------- scratch (device globals; no allocation) ----------------
__device__ float g_x[TT*CC];
__device__ float g_ln[TT*CC];
__device__ float g_big[TT*512];
__device__ float g_attn[TT*CC];
__device__ float g_xc[(TT/4)*512];

// ---------------- helpers ----------------
__device__ __forceinline__ uint32_t smem_u32(const void* p) {
    uint32_t a;
    asm("{ .reg .u64 t; cvta.to.shared.u64 t, %1; cvt.u32.u64 %0, t; }" : "=r"(a) : "l"(p));
    return a;
}
__device__ __forceinline__ void cp16(uint32_t dst, const void* src) {
    asm volatile("cp.async.cg.shared.global [%0], [%1], 16;" :: "r"(dst), "l"(src));
}
__device__ __forceinline__ void cp_commit() {
    asm volatile("cp.async.commit_group;" ::: "memory");
}
template<int N>
__device__ __forceinline__ void cp_wait() {
    asm volatile("cp.async.wait_group %0;" :: "n"(N) : "memory");
}
__device__ __forceinline__ void mma_tf32(float* c, const uint32_t* a, const uint32_t* b) {
    asm volatile(
        "mma.sync.aligned.m16n8k8.row.col.f32.tf32.tf32.f32 "
        "{%0,%1,%2,%3}, {%4,%5,%6,%7}, {%8,%9}, {%0,%1,%2,%3};"
        : "+f"(c[0]), "+f"(c[1]), "+f"(c[2]), "+f"(c[3])
        : "r"(a[0]), "r"(a[1]), "r"(a[2]), "r"(a[3]), "r"(b[0]), "r"(b[1]));
}
__device__ __forceinline__ void ldsm4(uint32_t* r, uint32_t addr) {
    asm volatile("ldmatrix.sync.aligned.m8n8.x4.shared.b16 {%0,%1,%2,%3}, [%4];"
        : "=r"(r[0]), "=r"(r[1]), "=r"(r[2]), "=r"(r[3]) : "r"(addr));
}
// round-to-nearest tf32 conversion (unbiased vs HW truncation)
__device__ __forceinline__ uint32_t cvt_tf32f(float x) {
    uint32_t y;
    asm("cvt.rna.tf32.f32 %0, %1;" : "=r"(y) : "f"(x));
    return y;
}
__device__ __forceinline__ uint32_t cvt_tf32b(uint32_t x) {
    uint32_t y;
    asm("cvt.rna.tf32.f32 %0, %1;" : "=r"(y) : "f"(__uint_as_float(x)));
    return y;
}

// window-ordered row -> natural token (reverse roll by +shift)
__device__ __forceinline__ int win_to_token(int m, int shift) {
    int b   = m / (NWIN*NTOK);
    int rem = m - b*(NWIN*NTOK);
    int win = rem >> 6;
    int n   = rem & 63;
    int wr = win / 12, wc = win - wr*12;
    int hp = wr*8 + (n >> 3);
    int wp = wc*8 + (n & 7);
    int h = hp + shift; if (h >= HH) h -= HH;
    int w = wp + shift; if (w >= WW) w -= WW;
    return b*(HH*WW) + h*WW + w;
}
// natural token -> window-ordered index
__device__ __forceinline__ int tok_to_win(int t, int shift) {
    int bi = t / (HH*WW);
    int hw = t - bi*(HH*WW);
    int h = hw / WW, w = hw - (hw/WW)*WW;
    int hp = h - shift; if (hp < 0) hp += HH;
    int wp = w - shift; if (wp < 0) wp += WW;
    return bi*(NWIN*NTOK) + ((hp>>3)*12 + (wp>>3))*NTOK + ((hp&7)*8 + (wp&7));
}

// ---------------- LN (warp per token), optional roll+window gather + raw copy ----------------
__global__ void __launch_bounds__(256) ln_kernel(
    const float* __restrict__ x, const float* __restrict__ g,
    const float* __restrict__ b, float* __restrict__ out,
    float* __restrict__ xcopy, int shift, int windowed)
{
    int warp = threadIdx.x >> 5;
    int lane = threadIdx.x & 31;
    int token = blockIdx.x*8 + warp;
    const float4* row = (const float4*)(x + (size_t)token*CC);
    float4 v = row[lane];
    if (xcopy) ((float4*)(xcopy + (size_t)token*CC))[lane] = v;
    float s = v.x + v.y + v.z + v.w;
    #pragma unroll
    for (int o = 16; o > 0; o >>= 1) s += __shfl_xor_sync(0xffffffffu, s, o);
    float m = s * (1.0f/128.0f);
    float dx = v.x - m, dy = v.y - m, dz = v.z - m, dw = v.w - m;
    float q = dx*dx + dy*dy + dz*dz + dw*dw;
    #pragma unroll
    for (int o = 16; o > 0; o >>= 1) q += __shfl_xor_sync(0xffffffffu, q, o);
    float inv = rsqrtf(q * (1.0f/128.0f) + 1e-5f);
    float4 gg = ((const float4*)g)[lane];
    float4 bb = ((const float4*)b)[lane];
    float4 r;
    r.x = dx*inv*gg.x + bb.x;
    r.y = dy*inv*gg.y + bb.y;
    r.z = dz*inv*gg.z + bb.z;
    r.w = dw*inv*gg.w + bb.w;
    int dest = token;
    if (windowed) dest = tok_to_win(token, shift);
    ((float4*)(out + (size_t)dest*CC))[lane] = r;
}

// ---------------- mma.sync tf32 GEMM (rna-rounded operands), fused epilogues ----------------
#define GBM 128
#define GBN 128
#define GBK 32
#define BSTR 132
#define AFLT (GBM*32)
#define BFLT (GBK*BSTR)
#define STAGEF (AFLT+BFLT)
#define STAGEB (STAGEF*4)
#define NSTAGE 3
#define GSMEM (NSTAGE*STAGEB)

template<int MODE, int K, int LNF>
__global__ void __launch_bounds__(256, 2) tgemm(
    const float* __restrict__ A, const float* __restrict__ Bw,
    const float* __restrict__ bias, float* __restrict__ out,
    const float* __restrict__ res,
    const float* __restrict__ lng, const float* __restrict__ lnb,
    float* __restrict__ lnout,
    int M, int N, int shift)
{
    extern __shared__ float sm[];
    uint32_t sb = smem_u32(sm);
    int tid = threadIdx.x;
    int wid = tid >> 5;
    int lane = tid & 31;
    int g = lane >> 2, q = lane & 3;
    int warp_m = wid >> 2, warp_n = wid & 3;
    int m0 = blockIdx.y * GBM, n0 = blockIdx.x * GBN;

    const float* Ab = A + (size_t)m0 * K;

    int arow = tid >> 3;
    int achk = tid & 7;
    int brow = tid >> 5, bc4 = (tid & 31) * 4;

    int rowlane = lane & 15;
    int hiBit = lane >> 4;
    int lo7 = lane & 7;

    float c[4][4][4];
    #pragma unroll
    for (int mt = 0; mt < 4; mt++)
        #pragma unroll
        for (int nt = 0; nt < 4; nt++)
            #pragma unroll
            for (int i = 0; i < 4; i++) c[mt][nt][i] = 0.0f;

    const int NC = K / GBK;

    auto load_tile = [&](int kb, int buf) {
        uint32_t sA = sb + buf*STAGEB;
        uint32_t sB = sA + AFLT*4;
        const float* Ap = Ab + kb*GBK;
        const float* Bp = Bw + (size_t)(kb*GBK)*N + n0;
        #pragma unroll
        for (int i = 0; i < 4; i++) {
            int r = arow + i*32;
            cp16(sA + (uint32_t)(r*8 + (achk ^ (r & 7)))*16, Ap + (size_t)r*K + achk*4);
        }
        #pragma unroll
        for (int i = 0; i < 4; i++) {
            int r = brow + i*8;
            cp16(sB + (uint32_t)(r*BSTR + bc4)*4, Bp + (size_t)r*N + bc4);
        }
        cp_commit();
    };

    load_tile(0, 0);
    if (NC > 1) load_tile(1, 1);

    int buf = 0;
    #pragma unroll 2
    for (int kb = 0; kb < NC; kb++) {
        if (kb == NC - 1) cp_wait<0>(); else cp_wait<NSTAGE-2>();
        __syncthreads();

        if (kb + 2 < NC) {
            int nbuf = buf + 2; if (nbuf >= NSTAGE) nbuf -= NSTAGE;
            load_tile(kb + 2, nbuf);
        }

        uint32_t aBase = sb + buf*STAGEB + (uint32_t)(warp_m*64 + rowlane)*128;
        const float* Bs_ = sm + buf*STAGEF + AFLT;

        #pragma unroll
        for (int ks = 0; ks < 4; ks++) {
            uint32_t physOff = ((uint32_t)((ks*2 + hiBit) ^ lo7)) << 4;
            uint32_t a[4][4], b[4][2];
            #pragma unroll
            for (int mt = 0; mt < 4; mt++) {
                ldsm4(a[mt], aBase + (uint32_t)mt*2048 + physOff);
                #pragma unroll
                for (int i = 0; i < 4; i++) a[mt][i] = cvt_tf32b(a[mt][i]);
            }
            #pragma unroll
            for (int nt = 0; nt < 4; nt++) {
                int col = warp_n*32 + nt*8 + g;
                b[nt][0] = cvt_tf32f(Bs_[(ks*8 + q)*BSTR + col]);
                b[nt][1] = cvt_tf32f(Bs_[(ks*8 + q + 4)*BSTR + col]);
            }
            #pragma unroll
            for (int mt = 0; mt < 4; mt++)
                #pragma unroll
                for (int nt = 0; nt < 4; nt++)
                    mma_tf32(c[mt][nt], a[mt], b[nt]);
        }
        buf++; if (buf >= NSTAGE) buf = 0;
    }

    if (LNF == 0) {
        float qscale = (MODE == 0 && n0 == 0) ? 0.17677669529663687f : 1.0f;
        #pragma unroll
        for (int mt = 0; mt < 4; mt++) {
            int r0 = m0 + warp_m*64 + mt*16 + g;
            int r1 = r0 + 8;
            int t0 = r0, t1 = r1;
            if (MODE == 1) { t0 = win_to_token(r0, shift); t1 = win_to_token(r1, shift); }
            #pragma unroll
            for (int nt = 0; nt < 4; nt++) {
                int cb = n0 + warp_n*32 + nt*8 + 2*q;
                float bx = 0.f, by = 0.f;
                if (MODE != 4) { float2 bv = *(const float2*)(bias + cb); bx = bv.x; by = bv.y; }
                float v0 = c[mt][nt][0] + bx, v1 = c[mt][nt][1] + by;
                float v2 = c[mt][nt][2] + bx, v3 = c[mt][nt][3] + by;
                if (MODE == 0) {
                    v0 *= qscale; v1 *= qscale; v2 *= qscale; v3 *= qscale;
                    float2 o0 = {v0, v1}, o1 = {v2, v3};
                    *(float2*)(out + (size_t)r0*N + cb) = o0;
                    *(float2*)(out + (size_t)r1*N + cb) = o1;
                } else if (MODE == 1) {
                    float2 rv0 = *(const float2*)(res + (size_t)t0*CC + cb);
                    float2 rv1 = *(const float2*)(res + (size_t)t1*CC + cb);
                    float2 o0 = {v0+rv0.x, v1+rv0.y}, o1 = {v2+rv1.x, v3+rv1.y};
                    *(float2*)(out + (size_t)t0*CC + cb) = o0;
                    *(float2*)(out + (size_t)t1*CC + cb) = o1;
                } else if (MODE == 2) {
                    float2 o0, o1;
                    o0.x = 0.5f*v0*(1.0f + erff(v0*0.7071067811865476f));
                    o0.y = 0.5f*v1*(1.0f + erff(v1*0.7071067811865476f));
                    o1.x = 0.5f*v2*(1.0f + erff(v2*0.7071067811865476f));
                    o1.y = 0.5f*v3*(1.0f + erff(v3*0.7071067811865476f));
                    *(float2*)(out + (size_t)r0*N + cb) = o0;
                    *(float2*)(out + (size_t)r1*N + cb) = o1;
                } else if (MODE == 3) {
                    float2 rv0 = *(const float2*)(res + (size_t)r0*N + cb);
                    float2 rv1 = *(const float2*)(res + (size_t)r1*N + cb);
                    float2 o0 = {v0+rv0.x, v1+rv0.y}, o1 = {v2+rv1.x, v3+rv1.y};
                    *(float2*)(out + (size_t)r0*N + cb) = o0;
                    *(float2*)(out + (size_t)r1*N + cb) = o1;
                } else {
                    float2 o0 = {v0, v1}, o1 = {v2, v3};
                    *(float2*)(out + (size_t)r0*N + cb) = o0;
                    *(float2*)(out + (size_t)r1*N + cb) = o1;
                }
            }
        }
    } else {
        // ---- LN-fused epilogue (MODE 1 or 3; N == 128, gridx == 1) ----
        int tok[4][2];
        float rs[4][2], rq[4][2];
        #pragma unroll
        for (int mt = 0; mt < 4; mt++) {
            int r0 = m0 + warp_m*64 + mt*16 + g;
            int r1 = r0 + 8;
            int t0 = (MODE == 1) ? win_to_token(r0, shift) : r0;
            int t1 = (MODE == 1) ? win_to_token(r1, shift) : r1;
            tok[mt][0] = t0; tok[mt][1] = t1;
            float s0 = 0.f, s1 = 0.f, q0 = 0.f, q1 = 0.f;
            #pragma unroll
            for (int nt = 0; nt < 4; nt++) {
                int cb = warp_n*32 + nt*8 + 2*q;
                float2 bv = *(const float2*)(bias + cb);
                float2 rv0 = *(const float2*)(res + (size_t)t0*CC + cb);
                float2 rv1 = *(const float2*)(res + (size_t)t1*CC + cb);
                float v0 = c[mt][nt][0] + bv.x + rv0.x;
                float v1 = c[mt][nt][1] + bv.y + rv0.y;
                float v2 = c[mt][nt][2] + bv.x + rv1.x;
                float v3 = c[mt][nt][3] + bv.y + rv1.y;
                c[mt][nt][0] = v0; c[mt][nt][1] = v1;
                c[mt][nt][2] = v2; c[mt][nt][3] = v3;
                s0 += v0 + v1; q0 += v0*v0 + v1*v1;
                s1 += v2 + v3; q1 += v2*v2 + v3*v3;
            }
            s0 += __shfl_xor_sync(0xffffffffu, s0, 1); s0 += __shfl_xor_sync(0xffffffffu, s0, 2);
            q0 += __shfl_xor_sync(0xffffffffu, q0, 1); q0 += __shfl_xor_sync(0xffffffffu, q0, 2);
            s1 += __shfl_xor_sync(0xffffffffu, s1, 1); s1 += __shfl_xor_sync(0xffffffffu, s1, 2);
            q1 += __shfl_xor_sync(0xffffffffu, q1, 1); q1 += __shfl_xor_sync(0xffffffffu, q1, 2);
            rs[mt][0] = s0; rq[mt][0] = q0;
            rs[mt][1] = s1; rq[mt][1] = q1;
        }
        __syncthreads();
        float* ps = sm;
        float* pq = sm + 512;
        if (q == 0) {
            #pragma unroll
            for (int mt = 0; mt < 4; mt++) {
                int lr0 = warp_m*64 + mt*16 + g;
                ps[warp_n*128 + lr0] = rs[mt][0];
                pq[warp_n*128 + lr0] = rq[mt][0];
                ps[warp_n*128 + lr0 + 8] = rs[mt][1];
                pq[warp_n*128 + lr0 + 8] = rq[mt][1];
            }
        }
        __syncthreads();
        #pragma unroll
        for (int mt = 0; mt < 4; mt++) {
            #pragma unroll
            for (int half = 0; half < 2; half++) {
                int lr = warp_m*64 + mt*16 + g + half*8;
                int t = tok[mt][half];
                float srow = ps[lr] + ps[128 + lr] + ps[256 + lr] + ps[384 + lr];
                float qrow = pq[lr] + pq[128 + lr] + pq[256 + lr] + pq[384 + lr];
                float mean = srow * (1.0f/128.0f);
                float var = qrow * (1.0f/128.0f) - mean*mean;
                float inv = rsqrtf(var + 1e-5f);
                int dest = (LNF == 1) ? t : tok_to_win(t, shift);
                #pragma unroll
                for (int nt = 0; nt < 4; nt++) {
                    int cb = warp_n*32 + nt*8 + 2*q;
                    float v0 = c[mt][nt][half*2+0];
                    float v1 = c[mt][nt][half*2+1];
                    float2 o = {v0, v1};
                    *(float2*)(out + (size_t)t*CC + cb) = o;
                    float2 lg = *(const float2*)(lng + cb);
                    float2 lb = *(const float2*)(lnb + cb);
                    float2 l;
                    l.x = (v0 - mean)*inv*lg.x + lb.x;
                    l.y = (v1 - mean)*inv*lg.y + lb.y;
                    *(float2*)(lnout + (size_t)dest*CC + cb) = l;
                }
            }
        }
    }
}

// ---------------- tensor-core windowed attention: one window per block ----------------
// 256 threads = 8 warps; warp w: head h = w>>1, row-half = w&1 (32 query rows = 2 m16 tiles).
// Q,K,V staged in smem [64][132]; S via m16n8k8 tf32; softmax in frags (unnormalized);
// P c-frag -> a-frag via shfl; PV via m16n8k8; 1/sum folded into O store.
#define ALSTR 132
#define ATILE (64*ALSTR)          // 8448 floats
#define ASMEM (3*ATILE*4)         // 101376 bytes

__global__ void __launch_bounds__(256) attn_tc_kernel(
    const float* __restrict__ qkv, float* __restrict__ out, int masked)
{
    extern __shared__ float smf[];
    float* qs = smf;
    float* ks = smf + ATILE;
    float* vs = smf + 2*ATILE;

    int tid = threadIdx.x;
    int win = blockIdx.x;
    const float* base = qkv + (size_t)win*NTOK*384;

    // cooperative stage: 64 rows x 128 cols each of Q,K,V
    for (int i = tid; i < 64*32; i += 256) {
        int r = i >> 5, c4 = (i & 31) * 4;
        const float* rowp = base + (size_t)r*384 + c4;
        *(float4*)(qs + r*ALSTR + c4) = *(const float4*)(rowp);
        *(float4*)(ks + r*ALSTR + c4) = *(const float4*)(rowp + 128);
        *(float4*)(vs + r*ALSTR + c4) = *(const float4*)(rowp + 256);
    }
    __syncthreads();

    int wid = tid >> 5, lane = tid & 31;
    int h = wid >> 1, mhalf = wid & 1;
    int g = lane >> 2, q = lane & 3;
    int hb = h*32;

    // mask geometry (uniform per block)
    int wloc = win % NWIN;
    int wr = wloc / 12, wc = wloc - wr*12;
    bool needmask = masked && (wr == 11 || wc == 11);

    const float NINF = __int_as_float(0xff800000);
    float* orow = out + (size_t)win*NTOK*CC;

    #pragma unroll
    for (int mt = 0; mt < 2; mt++) {
        int rowbase = mhalf*32 + mt*16;
        // Q a-frags (4 k-chunks)
        uint32_t qa[4][4];
        #pragma unroll
        for (int kc = 0; kc < 4; kc++) {
            int off = (rowbase + g)*ALSTR + hb + kc*8 + q;
            qa[kc][0] = cvt_tf32f(qs[off]);
            qa[kc][1] = cvt_tf32f(qs[off + 8*ALSTR]);
            qa[kc][2] = cvt_tf32f(qs[off + 4]);
            qa[kc][3] = cvt_tf32f(qs[off + 8*ALSTR + 4]);
        }
        // S = Q @ K^T  (16 x 64)
        float s[8][4];
        #pragma unroll
        for (int nt = 0; nt < 8; nt++) {
            s[nt][0] = s[nt][1] = s[nt][2] = s[nt][3] = 0.f;
            #pragma unroll
            for (int kc = 0; kc < 4; kc++) {
                int koff = (nt*8 + g)*ALSTR + hb + kc*8 + q;
                uint32_t b[2];
                b[0] = cvt_tf32f(ks[koff]);
                b[1] = cvt_tf32f(ks[koff + 4]);
                mma_tf32(s[nt], qa[kc], b);
            }
        }
        // mask
        if (needmask) {
            int t0 = rowbase + g, t1 = t0 + 8;
            int lr0 = ((wr == 11) ? (((t0 >> 3) < 4) ? 1 : 2) : 0)*3 + ((wc == 11) ? (((t0 & 7) < 4) ? 1 : 2) : 0);
            int lr1 = ((wr == 11) ? (((t1 >> 3) < 4) ? 1 : 2) : 0)*3 + ((wc == 11) ? (((t1 & 7) < 4) ? 1 : 2) : 0);
            #pragma unroll
            for (int nt = 0; nt < 8; nt++) {
                int ca = nt*8 + 2*q, cb2 = ca + 1;
                int lca = ((wr == 11) ? ((nt < 4) ? 1 : 2) : 0)*3 + ((wc == 11) ? (((ca & 7) < 4) ? 1 : 2) : 0);
                int lcb = ((wr == 11) ? ((nt < 4) ? 1 : 2) : 0)*3 + ((wc == 11) ? (((cb2 & 7) < 4) ? 1 : 2) : 0);
                if (lca != lr0) s[nt][0] = NINF;
                if (lcb != lr0) s[nt][1] = NINF;
                if (lca != lr1) s[nt][2] = NINF;
                if (lcb != lr1) s[nt][3] = NINF;
            }
        }
        // softmax (unnormalized): rows g and g+8
        float mx0 = NINF, mx1 = NINF;
        #pragma unroll
        for (int nt = 0; nt < 8; nt++) {
            mx0 = fmaxf(mx0, fmaxf(s[nt][0], s[nt][1]));
            mx1 = fmaxf(mx1, fmaxf(s[nt][2], s[nt][3]));
        }
        mx0 = fmaxf(mx0, __shfl_xor_sync(0xffffffffu, mx0, 1));
        mx0 = fmaxf(mx0, __shfl_xor_sync(0xffffffffu, mx0, 2));
        mx1 = fmaxf(mx1, __shfl_xor_sync(0xffffffffu, mx1, 1));
        mx1 = fmaxf(mx1, __shfl_xor_sync(0xffffffffu, mx1, 2));
        float sum0 = 0.f, sum1 = 0.f;
        #pragma unroll
        for (int nt = 0; nt < 8; nt++) {
            s[nt][0] = __expf(s[nt][0] - mx0);
            s[nt][1] = __expf(s[nt][1] - mx0);
            s[nt][2] = __expf(s[nt][2] - mx1);
            s[nt][3] = __expf(s[nt][3] - mx1);
            sum0 += s[nt][0] + s[nt][1];
            sum1 += s[nt][2] + s[nt][3];
        }
        sum0 += __shfl_xor_sync(0xffffffffu, sum0, 1);
        sum0 += __shfl_xor_sync(0xffffffffu, sum0, 2);
        sum1 += __shfl_xor_sync(0xffffffffu, sum1, 1);
        sum1 += __shfl_xor_sync(0xffffffffu, sum1, 2);
        float inv0 = 1.0f / sum0, inv1 = 1.0f / sum1;

        // O = P @ V  (16 x 32)
        float o[4][4];
        #pragma unroll
        for (int nt = 0; nt < 4; nt++) { o[nt][0]=o[nt][1]=o[nt][2]=o[nt][3]=0.f; }
        int sl = (g << 2) + (q >> 1);
        bool odd = (q & 1);
        #pragma unroll
        for (int kc = 0; kc < 8; kc++) {
            float x0 = __shfl_sync(0xffffffffu, s[kc][0], sl);
            float x1 = __shfl_sync(0xffffffffu, s[kc][1], sl);
            float y0 = __shfl_sync(0xffffffffu, s[kc][2], sl);
            float y1 = __shfl_sync(0xffffffffu, s[kc][3], sl);
            float x2 = __shfl_sync(0xffffffffu, s[kc][0], sl + 2);
            float x3 = __shfl_sync(0xffffffffu, s[kc][1], sl + 2);
            float y2 = __shfl_sync(0xffffffffu, s[kc][2], sl + 2);
            float y3 = __shfl_sync(0xffffffffu, s[kc][3], sl + 2);
            uint32_t pa[4];
            pa[0] = cvt_tf32f(odd ? x1 : x0);
            pa[1] = cvt_tf32f(odd ? y1 : y0);
            pa[2] = cvt_tf32f(odd ? x3 : x2);
            pa[3] = cvt_tf32f(odd ? y3 : y2);
            #pragma unroll
            for (int nt = 0; nt < 4; nt++) {
                int voff0 = (kc*8 + q)*ALSTR + hb + nt*8 + g;
                int voff1 = (kc*8 + q + 4)*ALSTR + hb + nt*8 + g;
                uint32_t b[2];
                b[0] = cvt_tf32f(vs[voff0]);
                b[1] = cvt_tf32f(vs[voff1]);
                mma_tf32(o[nt], pa, b);
            }
        }
        // write (scaled by 1/sum)
        #pragma unroll
        for (int nt = 0; nt < 4; nt++) {
            int col = hb + nt*8 + 2*q;
            float2 o0 = {o[nt][0]*inv0, o[nt][1]*inv0};
            float2 o1 = {o[nt][2]*inv1, o[nt][3]*inv1};
            *(float2*)(orow + (size_t)(rowbase + g)*CC + col) = o0;
            *(float2*)(orow + (size_t)(rowbase + g + 8)*CC + col) = o1;
        }
    }
}

// ---------------- patch-merge gather + LN over 512 ----------------
__global__ void __launch_bounds__(128) merge_ln_kernel(
    const float* __restrict__ x, const float* __restrict__ g,
    const float* __restrict__ b, float* __restrict__ out)
{
    __shared__ float sred[8];
    int token = blockIdx.x;
    int b_ = token / 2304;
    int ij = token - b_*2304;
    int i2 = ij / 48, j2 = ij - (ij/48)*48;
    int tid = threadIdx.x;
    int warp = tid >> 5, lane = tid & 31;
    int chunk = tid >> 5;
    int cc = (tid & 31) * 4;
    int dh = chunk & 1, dw = chunk >> 1;
    int h = 2*i2 + dh, w = 2*j2 + dw;
    const float* src = x + ((size_t)(b_*(HH*WW) + h*WW + w))*CC + cc;
    float4 v = *(const float4*)src;

    float s = v.x + v.y + v.z + v.w;
    #pragma unroll
    for (int o = 16; o > 0; o >>= 1) s += __shfl_xor_sync(0xffffffffu, s, o);
    if (lane == 0) sred[warp] = s;
    __syncthreads();
    float m = (sred[0]+sred[1]+sred[2]+sred[3]) * (1.0f/512.0f);

    float dx = v.x-m, dy = v.y-m, dz = v.z-m, dwv = v.w-m;
    float q = dx*dx + dy*dy + dz*dz + dwv*dwv;
    #pragma unroll
    for (int o = 16; o > 0; o >>= 1) q += __shfl_xor_sync(0xffffffffu, q, o);
    if (lane == 0) sred[4+warp] = q;
    __syncthreads();
    float var = (sred[4]+sred[5]+sred[6]+sred[7]) * (1.0f/512.0f);
    float inv = rsqrtf(var + 1e-5f);

    int oc = tid*4;
    float4 gg = *(const float4*)(g + oc);
    float4 bb = *(const float4*)(b + oc);
    float4 r;
    r.x = dx*inv*gg.x + bb.x;
    r.y = dy*inv*gg.y + bb.y;
    r.z = dz*inv*gg.z + bb.z;
    r.w = dwv*inv*gg.w + bb.w;
    *(float4*)(out + (size_t)token*512 + oc) = r;
}

// ---------------- host orchestration ----------------
extern "C" void kernel_launch(void* const* d_in, const int* in_sizes, int n_in,
                              void* d_out, int out_size)
{
    (void)in_sizes; (void)n_in; (void)out_size;
    const float* P[28];
    for (int i = 0; i < 28; i++) P[i] = (const float*)d_in[i];
    const float* mln_g = P[25];
    const float* mln_b = P[26];
    const float* red_w = P[27];

    float *px, *pln, *pbig, *pattn, *pxc;
    cudaGetSymbolAddress((void**)&px,   g_x);
    cudaGetSymbolAddress((void**)&pln,  g_ln);
    cudaGetSymbolAddress((void**)&pbig, g_big);
    cudaGetSymbolAddress((void**)&pattn,g_attn);
    cudaGetSymbolAddress((void**)&pxc,  g_xc);

    static int smem_set = 0;
    if (!smem_set) {
        cudaFuncSetAttribute(tgemm<0,128,0>, cudaFuncAttributeMaxDynamicSharedMemorySize, GSMEM);
        cudaFuncSetAttribute(tgemm<1,128,1>, cudaFuncAttributeMaxDynamicSharedMemorySize, GSMEM);
        cudaFuncSetAttribute(tgemm<2,128,0>, cudaFuncAttributeMaxDynamicSharedMemorySize, GSMEM);
        cudaFuncSetAttribute(tgemm<3,512,2>, cudaFuncAttributeMaxDynamicSharedMemorySize, GSMEM);
        cudaFuncSetAttribute(tgemm<3,512,0>, cudaFuncAttributeMaxDynamicSharedMemorySize, GSMEM);
        cudaFuncSetAttribute(tgemm<4,512,0>, cudaFuncAttributeMaxDynamicSharedMemorySize, GSMEM);
        cudaFuncSetAttribute(attn_tc_kernel, cudaFuncAttributeMaxDynamicSharedMemorySize, ASMEM);
        smem_set = 1;
    }

    // ---- block 0 (W-MSA, shift 0) ----
    ln_kernel<<<TT/8, 256>>>((const float*)d_in[0], P[1], P[2], pln, px, 0, 1);
    tgemm<0,128,0><<<dim3(3, TT/128), 256, GSMEM>>>(pln, P[3], P[4], pbig, nullptr, nullptr, nullptr, nullptr, TT, 384, 0);
    attn_tc_kernel<<<WTOT, 256, ASMEM>>>(pbig, pattn, 0);
    tgemm<1,128,1><<<dim3(1, TT/128), 256, GSMEM>>>(pattn, P[5], P[6], px, px, P[7], P[8], pln, TT, 128, 0);
    tgemm<2,128,0><<<dim3(4, TT/128), 256, GSMEM>>>(pln, P[9], P[10], pbig, nullptr, nullptr, nullptr, nullptr, TT, 512, 0);
    tgemm<3,512,2><<<dim3(1, TT/128), 256, GSMEM>>>(pbig, P[11], P[12], px, px, P[13], P[14], pln, TT, 128, 4);

    // ---- block 1 (SW-MSA, shift 4) ----
    tgemm<0,128,0><<<dim3(3, TT/128), 256, GSMEM>>>(pln, P[15], P[16], pbig, nullptr, nullptr, nullptr, nullptr, TT, 384, 0);
    attn_tc_kernel<<<WTOT, 256, ASMEM>>>(pbig, pattn, 1);
    tgemm<1,128,1><<<dim3(1, TT/128), 256, GSMEM>>>(pattn, P[17], P[18], px, px, P[19], P[20], pln, TT, 128, 4);
    tgemm<2,128,0><<<dim3(4, TT/128), 256, GSMEM>>>(pln, P[21], P[22], pbig, nullptr, nullptr, nullptr, nullptr, TT, 512, 0);
    tgemm<3,512,0><<<dim3(1, TT/128), 256, GSMEM>>>(pbig, P[23], P[24], px, px, nullptr, nullptr, nullptr, TT, 128, 0);

    merge_ln_kernel<<<TT/4, 128>>>(px, mln_g, mln_b, pxc);
    tgemm<4,512,0><<<dim3(2, (TT/4)/128), 256, GSMEM>>>(pxc, red_w, nullptr, (float*)d_out, nullptr, nullptr, nullptr, nullptr, TT/4, 256, 0);
}

// round 10
// speedup vs baseline: 1.7173x; 1.7173x over previous
#include <cuda_runtime.h>
#include <cuda_bf16.h>
#include <math.h>
#include <stdint.h>

// ---------------- problem constants ----------------
#define BB   8
#define HH   96
#define WW   96
#define CC   128
#define TT   (BB*HH*WW)      // 73728 tokens
#define NWIN 144             // 12*12 windows per image
#define WTOT (BB*NWIN)       // 1152 windows
#define NTOK 64              // tokens per window

// ---------------- scratch (device globals; no allocation) ----------------
__device__ float g_x[TT*CC];
__device__ float g_ln[TT*CC];
__device__ float g_big[TT*512];
__device__ float g_attn[TT*CC];
__device__ float g_xc[(TT/4)*512];

// ---------------- helpers ----------------
__device__ __forceinline__ uint32_t smem_u32(const void* p) {
    uint32_t a;
    asm("{ .reg .u64 t; cvta.to.shared.u64 t, %1; cvt.u32.u64 %0, t; }" : "=r"(a) : "l"(p));
    return a;
}
__device__ __forceinline__ void cp16(uint32_t dst, const void* src) {
    asm volatile("cp.async.cg.shared.global [%0], [%1], 16;" :: "r"(dst), "l"(src));
}
__device__ __forceinline__ void cp_commit() {
    asm volatile("cp.async.commit_group;" ::: "memory");
}
template<int N>
__device__ __forceinline__ void cp_wait() {
    asm volatile("cp.async.wait_group %0;" :: "n"(N) : "memory");
}
__device__ __forceinline__ void mma_tf32(float* c, const uint32_t* a, const uint32_t* b) {
    asm volatile(
        "mma.sync.aligned.m16n8k8.row.col.f32.tf32.tf32.f32 "
        "{%0,%1,%2,%3}, {%4,%5,%6,%7}, {%8,%9}, {%0,%1,%2,%3};"
        : "+f"(c[0]), "+f"(c[1]), "+f"(c[2]), "+f"(c[3])
        : "r"(a[0]), "r"(a[1]), "r"(a[2]), "r"(a[3]), "r"(b[0]), "r"(b[1]));
}
__device__ __forceinline__ void ldsm4(uint32_t* r, uint32_t addr) {
    asm volatile("ldmatrix.sync.aligned.m8n8.x4.shared.b16 {%0,%1,%2,%3}, [%4];"
        : "=r"(r[0]), "=r"(r[1]), "=r"(r[2]), "=r"(r[3]) : "r"(addr));
}
__device__ __forceinline__ uint32_t cvt_tf32f(float x) {
    uint32_t y;
    asm("cvt.rna.tf32.f32 %0, %1;" : "=r"(y) : "f"(x));
    return y;
}

// window-ordered row -> natural token (reverse roll by +shift)
__device__ __forceinline__ int win_to_token(int m, int shift) {
    int b   = m / (NWIN*NTOK);
    int rem = m - b*(NWIN*NTOK);
    int win = rem >> 6;
    int n   = rem & 63;
    int wr = win / 12, wc = win - wr*12;
    int hp = wr*8 + (n >> 3);
    int wp = wc*8 + (n & 7);
    int h = hp + shift; if (h >= HH) h -= HH;
    int w = wp + shift; if (w >= WW) w -= WW;
    return b*(HH*WW) + h*WW + w;
}
// natural token -> window-ordered index
__device__ __forceinline__ int tok_to_win(int t, int shift) {
    int bi = t / (HH*WW);
    int hw = t - bi*(HH*WW);
    int h = hw / WW, w = hw - (hw/WW)*WW;
    int hp = h - shift; if (hp < 0) hp += HH;
    int wp = w - shift; if (wp < 0) wp += WW;
    return bi*(NWIN*NTOK) + ((hp>>3)*12 + (wp>>3))*NTOK + ((hp&7)*8 + (wp&7));
}

// ---------------- LN (warp per token), optional roll+window gather + raw copy ----------------
__global__ void __launch_bounds__(256) ln_kernel(
    const float* __restrict__ x, const float* __restrict__ g,
    const float* __restrict__ b, float* __restrict__ out,
    float* __restrict__ xcopy, int shift, int windowed)
{
    int warp = threadIdx.x >> 5;
    int lane = threadIdx.x & 31;
    int token = blockIdx.x*8 + warp;
    const float4* row = (const float4*)(x + (size_t)token*CC);
    float4 v = row[lane];
    if (xcopy) ((float4*)(xcopy + (size_t)token*CC))[lane] = v;
    float s = v.x + v.y + v.z + v.w;
    #pragma unroll
    for (int o = 16; o > 0; o >>= 1) s += __shfl_xor_sync(0xffffffffu, s, o);
    float m = s * (1.0f/128.0f);
    float dx = v.x - m, dy = v.y - m, dz = v.z - m, dw = v.w - m;
    float q = dx*dx + dy*dy + dz*dz + dw*dw;
    #pragma unroll
    for (int o = 16; o > 0; o >>= 1) q += __shfl_xor_sync(0xffffffffu, q, o);
    float inv = rsqrtf(q * (1.0f/128.0f) + 1e-5f);
    float4 gg = ((const float4*)g)[lane];
    float4 bb = ((const float4*)b)[lane];
    float4 r;
    r.x = dx*inv*gg.x + bb.x;
    r.y = dy*inv*gg.y + bb.y;
    r.z = dz*inv*gg.z + bb.z;
    r.w = dw*inv*gg.w + bb.w;
    int dest = token;
    if (windowed) dest = tok_to_win(token, shift);
    ((float4*)(out + (size_t)dest*CC))[lane] = r;
}

// ---------------- mma.sync tf32 GEMM (raw-bit feed), fused epilogues ----------------
// MODE 0: qkv (+bias, qscale on n0==0, rna-rounded output for TC attention)
// MODE 1: proj (+bias, scatter+res) 2: fc1 (+bias, GELU) 3: fc2 (+bias, res) 4: plain
// LNF: 0 none; 1 also write LN(x); 2 also write LN(x) window-gathered with shift.
#define GBM 128
#define GBN 128
#define GBK 32
#define BSTR 132
#define AFLT (GBM*32)
#define BFLT (GBK*BSTR)
#define STAGEF (AFLT+BFLT)
#define STAGEB (STAGEF*4)
#define NSTAGE 3
#define GSMEM (NSTAGE*STAGEB)

template<int MODE, int K, int LNF>
__global__ void __launch_bounds__(256, 2) tgemm(
    const float* __restrict__ A, const float* __restrict__ Bw,
    const float* __restrict__ bias, float* __restrict__ out,
    const float* __restrict__ res,
    const float* __restrict__ lng, const float* __restrict__ lnb,
    float* __restrict__ lnout,
    int M, int N, int shift)
{
    extern __shared__ float sm[];
    uint32_t sb = smem_u32(sm);
    int tid = threadIdx.x;
    int wid = tid >> 5;
    int lane = tid & 31;
    int g = lane >> 2, q = lane & 3;
    int warp_m = wid >> 2, warp_n = wid & 3;
    int m0 = blockIdx.y * GBM, n0 = blockIdx.x * GBN;

    const float* Ab = A + (size_t)m0 * K;

    int arow = tid >> 3;
    int achk = tid & 7;
    int brow = tid >> 5, bc4 = (tid & 31) * 4;

    int rowlane = lane & 15;
    int hiBit = lane >> 4;
    int lo7 = lane & 7;

    float c[4][4][4];
    #pragma unroll
    for (int mt = 0; mt < 4; mt++)
        #pragma unroll
        for (int nt = 0; nt < 4; nt++)
            #pragma unroll
            for (int i = 0; i < 4; i++) c[mt][nt][i] = 0.0f;

    const int NC = K / GBK;

    auto load_tile = [&](int kb, int buf) {
        uint32_t sA = sb + buf*STAGEB;
        uint32_t sB = sA + AFLT*4;
        const float* Ap = Ab + kb*GBK;
        const float* Bp = Bw + (size_t)(kb*GBK)*N + n0;
        #pragma unroll
        for (int i = 0; i < 4; i++) {
            int r = arow + i*32;
            cp16(sA + (uint32_t)(r*8 + (achk ^ (r & 7)))*16, Ap + (size_t)r*K + achk*4);
        }
        #pragma unroll
        for (int i = 0; i < 4; i++) {
            int r = brow + i*8;
            cp16(sB + (uint32_t)(r*BSTR + bc4)*4, Bp + (size_t)r*N + bc4);
        }
        cp_commit();
    };

    load_tile(0, 0);
    if (NC > 1) load_tile(1, 1);

    int buf = 0;
    #pragma unroll 2
    for (int kb = 0; kb < NC; kb++) {
        if (kb == NC - 1) cp_wait<0>(); else cp_wait<NSTAGE-2>();
        __syncthreads();

        if (kb + 2 < NC) {
            int nbuf = buf + 2; if (nbuf >= NSTAGE) nbuf -= NSTAGE;
            load_tile(kb + 2, nbuf);
        }

        uint32_t aBase = sb + buf*STAGEB + (uint32_t)(warp_m*64 + rowlane)*128;
        const float* Bs_ = sm + buf*STAGEF + AFLT;

        #pragma unroll
        for (int ks = 0; ks < 4; ks++) {
            uint32_t physOff = ((uint32_t)((ks*2 + hiBit) ^ lo7)) << 4;
            uint32_t a[4][4], b[4][2];
            #pragma unroll
            for (int mt = 0; mt < 4; mt++)
                ldsm4(a[mt], aBase + (uint32_t)mt*2048 + physOff);
            #pragma unroll
            for (int nt = 0; nt < 4; nt++) {
                int col = warp_n*32 + nt*8 + g;
                b[nt][0] = __float_as_uint(Bs_[(ks*8 + q)*BSTR + col]);
                b[nt][1] = __float_as_uint(Bs_[(ks*8 + q + 4)*BSTR + col]);
            }
            #pragma unroll
            for (int mt = 0; mt < 4; mt++)
                #pragma unroll
                for (int nt = 0; nt < 4; nt++)
                    mma_tf32(c[mt][nt], a[mt], b[nt]);
        }
        buf++; if (buf >= NSTAGE) buf = 0;
    }

    if (LNF == 0) {
        float qscale = (MODE == 0 && n0 == 0) ? 0.17677669529663687f : 1.0f;
        #pragma unroll
        for (int mt = 0; mt < 4; mt++) {
            int r0 = m0 + warp_m*64 + mt*16 + g;
            int r1 = r0 + 8;
            int t0 = r0, t1 = r1;
            if (MODE == 1) { t0 = win_to_token(r0, shift); t1 = win_to_token(r1, shift); }
            #pragma unroll
            for (int nt = 0; nt < 4; nt++) {
                int cb = n0 + warp_n*32 + nt*8 + 2*q;
                float bx = 0.f, by = 0.f;
                if (MODE != 4) { float2 bv = *(const float2*)(bias + cb); bx = bv.x; by = bv.y; }
                float v0 = c[mt][nt][0] + bx, v1 = c[mt][nt][1] + by;
                float v2 = c[mt][nt][2] + bx, v3 = c[mt][nt][3] + by;
                if (MODE == 0) {
                    // rna-round so TC attention gets unbiased tf32 operands for free
                    v0 = __uint_as_float(cvt_tf32f(v0*qscale));
                    v1 = __uint_as_float(cvt_tf32f(v1*qscale));
                    v2 = __uint_as_float(cvt_tf32f(v2*qscale));
                    v3 = __uint_as_float(cvt_tf32f(v3*qscale));
                    float2 o0 = {v0, v1}, o1 = {v2, v3};
                    *(float2*)(out + (size_t)r0*N + cb) = o0;
                    *(float2*)(out + (size_t)r1*N + cb) = o1;
                } else if (MODE == 1) {
                    float2 rv0 = *(const float2*)(res + (size_t)t0*CC + cb);
                    float2 rv1 = *(const float2*)(res + (size_t)t1*CC + cb);
                    float2 o0 = {v0+rv0.x, v1+rv0.y}, o1 = {v2+rv1.x, v3+rv1.y};
                    *(float2*)(out + (size_t)t0*CC + cb) = o0;
                    *(float2*)(out + (size_t)t1*CC + cb) = o1;
                } else if (MODE == 2) {
                    float2 o0, o1;
                    o0.x = 0.5f*v0*(1.0f + erff(v0*0.7071067811865476f));
                    o0.y = 0.5f*v1*(1.0f + erff(v1*0.7071067811865476f));
                    o1.x = 0.5f*v2*(1.0f + erff(v2*0.7071067811865476f));
                    o1.y = 0.5f*v3*(1.0f + erff(v3*0.7071067811865476f));
                    *(float2*)(out + (size_t)r0*N + cb) = o0;
                    *(float2*)(out + (size_t)r1*N + cb) = o1;
                } else if (MODE == 3) {
                    float2 rv0 = *(const float2*)(res + (size_t)r0*N + cb);
                    float2 rv1 = *(const float2*)(res + (size_t)r1*N + cb);
                    float2 o0 = {v0+rv0.x, v1+rv0.y}, o1 = {v2+rv1.x, v3+rv1.y};
                    *(float2*)(out + (size_t)r0*N + cb) = o0;
                    *(float2*)(out + (size_t)r1*N + cb) = o1;
                } else {
                    float2 o0 = {v0, v1}, o1 = {v2, v3};
                    *(float2*)(out + (size_t)r0*N + cb) = o0;
                    *(float2*)(out + (size_t)r1*N + cb) = o1;
                }
            }
        }
    } else {
        // ---- LN-fused epilogue (MODE 1 or 3; N == 128, gridx == 1) ----
        int tok[4][2];
        float rs[4][2], rq[4][2];
        #pragma unroll
        for (int mt = 0; mt < 4; mt++) {
            int r0 = m0 + warp_m*64 + mt*16 + g;
            int r1 = r0 + 8;
            int t0 = (MODE == 1) ? win_to_token(r0, shift) : r0;
            int t1 = (MODE == 1) ? win_to_token(r1, shift) : r1;
            tok[mt][0] = t0; tok[mt][1] = t1;
            float s0 = 0.f, s1 = 0.f, q0 = 0.f, q1 = 0.f;
            #pragma unroll
            for (int nt = 0; nt < 4; nt++) {
                int cb = warp_n*32 + nt*8 + 2*q;
                float2 bv = *(const float2*)(bias + cb);
                float2 rv0 = *(const float2*)(res + (size_t)t0*CC + cb);
                float2 rv1 = *(const float2*)(res + (size_t)t1*CC + cb);
                float v0 = c[mt][nt][0] + bv.x + rv0.x;
                float v1 = c[mt][nt][1] + bv.y + rv0.y;
                float v2 = c[mt][nt][2] + bv.x + rv1.x;
                float v3 = c[mt][nt][3] + bv.y + rv1.y;
                c[mt][nt][0] = v0; c[mt][nt][1] = v1;
                c[mt][nt][2] = v2; c[mt][nt][3] = v3;
                s0 += v0 + v1; q0 += v0*v0 + v1*v1;
                s1 += v2 + v3; q1 += v2*v2 + v3*v3;
            }
            s0 += __shfl_xor_sync(0xffffffffu, s0, 1); s0 += __shfl_xor_sync(0xffffffffu, s0, 2);
            q0 += __shfl_xor_sync(0xffffffffu, q0, 1); q0 += __shfl_xor_sync(0xffffffffu, q0, 2);
            s1 += __shfl_xor_sync(0xffffffffu, s1, 1); s1 += __shfl_xor_sync(0xffffffffu, s1, 2);
            q1 += __shfl_xor_sync(0xffffffffu, q1, 1); q1 += __shfl_xor_sync(0xffffffffu, q1, 2);
            rs[mt][0] = s0; rq[mt][0] = q0;
            rs[mt][1] = s1; rq[mt][1] = q1;
        }
        __syncthreads();
        float* ps = sm;
        float* pq = sm + 512;
        if (q == 0) {
            #pragma unroll
            for (int mt = 0; mt < 4; mt++) {
                int lr0 = warp_m*64 + mt*16 + g;
                ps[warp_n*128 + lr0] = rs[mt][0];
                pq[warp_n*128 + lr0] = rq[mt][0];
                ps[warp_n*128 + lr0 + 8] = rs[mt][1];
                pq[warp_n*128 + lr0 + 8] = rq[mt][1];
            }
        }
        __syncthreads();
        #pragma unroll
        for (int mt = 0; mt < 4; mt++) {
            #pragma unroll
            for (int half = 0; half < 2; half++) {
                int lr = warp_m*64 + mt*16 + g + half*8;
                int t = tok[mt][half];
                float srow = ps[lr] + ps[128 + lr] + ps[256 + lr] + ps[384 + lr];
                float qrow = pq[lr] + pq[128 + lr] + pq[256 + lr] + pq[384 + lr];
                float mean = srow * (1.0f/128.0f);
                float var = qrow * (1.0f/128.0f) - mean*mean;
                float inv = rsqrtf(var + 1e-5f);
                int dest = (LNF == 1) ? t : tok_to_win(t, shift);
                #pragma unroll
                for (int nt = 0; nt < 4; nt++) {
                    int cb = warp_n*32 + nt*8 + 2*q;
                    float v0 = c[mt][nt][half*2+0];
                    float v1 = c[mt][nt][half*2+1];
                    float2 o = {v0, v1};
                    *(float2*)(out + (size_t)t*CC + cb) = o;
                    float2 lg = *(const float2*)(lng + cb);
                    float2 lb = *(const float2*)(lnb + cb);
                    float2 l;
                    l.x = (v0 - mean)*inv*lg.x + lb.x;
                    l.y = (v1 - mean)*inv*lg.y + lb.y;
                    *(float2*)(lnout + (size_t)dest*CC + cb) = l;
                }
            }
        }
    }
}

// ---------------- tensor-core windowed attention (verified layout, raw-bit QKV feed) ----------------
#define ALSTR 132
#define ATILE (64*ALSTR)
#define ASMEM (3*ATILE*4)

__global__ void __launch_bounds__(256) attn_tc_kernel(
    const float* __restrict__ qkv, float* __restrict__ out, int masked)
{
    extern __shared__ float smf[];
    float* qs = smf;
    float* ks = smf + ATILE;
    float* vs = smf + 2*ATILE;

    int tid = threadIdx.x;
    int win = blockIdx.x;
    const float* base = qkv + (size_t)win*NTOK*384;

    for (int i = tid; i < 64*32; i += 256) {
        int r = i >> 5, c4 = (i & 31) * 4;
        const float* rowp = base + (size_t)r*384 + c4;
        *(float4*)(qs + r*ALSTR + c4) = *(const float4*)(rowp);
        *(float4*)(ks + r*ALSTR + c4) = *(const float4*)(rowp + 128);
        *(float4*)(vs + r*ALSTR + c4) = *(const float4*)(rowp + 256);
    }
    __syncthreads();

    int wid = tid >> 5, lane = tid & 31;
    int h = wid >> 1, mhalf = wid & 1;
    int g = lane >> 2, q = lane & 3;
    int hb = h*32;

    int wloc = win % NWIN;
    int wr = wloc / 12, wc = wloc - wr*12;
    bool needmask = masked && (wr == 11 || wc == 11);

    const float NINF = __int_as_float(0xff800000);
    float* orow = out + (size_t)win*NTOK*CC;

    #pragma unroll
    for (int mt = 0; mt < 2; mt++) {
        int rowbase = mhalf*32 + mt*16;
        uint32_t qa[4][4];
        #pragma unroll
        for (int kc = 0; kc < 4; kc++) {
            int off = (rowbase + g)*ALSTR + hb + kc*8 + q;
            qa[kc][0] = __float_as_uint(qs[off]);
            qa[kc][1] = __float_as_uint(qs[off + 8*ALSTR]);
            qa[kc][2] = __float_as_uint(qs[off + 4]);
            qa[kc][3] = __float_as_uint(qs[off + 8*ALSTR + 4]);
        }
        float s[8][4];
        #pragma unroll
        for (int nt = 0; nt < 8; nt++) {
            s[nt][0] = s[nt][1] = s[nt][2] = s[nt][3] = 0.f;
            #pragma unroll
            for (int kc = 0; kc < 4; kc++) {
                int koff = (nt*8 + g)*ALSTR + hb + kc*8 + q;
                uint32_t b[2];
                b[0] = __float_as_uint(ks[koff]);
                b[1] = __float_as_uint(ks[koff + 4]);
                mma_tf32(s[nt], qa[kc], b);
            }
        }
        if (needmask) {
            int t0 = rowbase + g, t1 = t0 + 8;
            int lr0 = ((wr == 11) ? (((t0 >> 3) < 4) ? 1 : 2) : 0)*3 + ((wc == 11) ? (((t0 & 7) < 4) ? 1 : 2) : 0);
            int lr1 = ((wr == 11) ? (((t1 >> 3) < 4) ? 1 : 2) : 0)*3 + ((wc == 11) ? (((t1 & 7) < 4) ? 1 : 2) : 0);
            #pragma unroll
            for (int nt = 0; nt < 8; nt++) {
                int ca = nt*8 + 2*q, cb2 = ca + 1;
                int lca = ((wr == 11) ? ((nt < 4) ? 1 : 2) : 0)*3 + ((wc == 11) ? (((ca & 7) < 4) ? 1 : 2) : 0);
                int lcb = ((wr == 11) ? ((nt < 4) ? 1 : 2) : 0)*3 + ((wc == 11) ? (((cb2 & 7) < 4) ? 1 : 2) : 0);
                if (lca != lr0) s[nt][0] = NINF;
                if (lcb != lr0) s[nt][1] = NINF;
                if (lca != lr1) s[nt][2] = NINF;
                if (lcb != lr1) s[nt][3] = NINF;
            }
        }
        float mx0 = NINF, mx1 = NINF;
        #pragma unroll
        for (int nt = 0; nt < 8; nt++) {
            mx0 = fmaxf(mx0, fmaxf(s[nt][0], s[nt][1]));
            mx1 = fmaxf(mx1, fmaxf(s[nt][2], s[nt][3]));
        }
        mx0 = fmaxf(mx0, __shfl_xor_sync(0xffffffffu, mx0, 1));
        mx0 = fmaxf(mx0, __shfl_xor_sync(0xffffffffu, mx0, 2));
        mx1 = fmaxf(mx1, __shfl_xor_sync(0xffffffffu, mx1, 1));
        mx1 = fmaxf(mx1, __shfl_xor_sync(0xffffffffu, mx1, 2));
        float sum0 = 0.f, sum1 = 0.f;
        #pragma unroll
        for (int nt = 0; nt < 8; nt++) {
            s[nt][0] = __expf(s[nt][0] - mx0);
            s[nt][1] = __expf(s[nt][1] - mx0);
            s[nt][2] = __expf(s[nt][2] - mx1);
            s[nt][3] = __expf(s[nt][3] - mx1);
            sum0 += s[nt][0] + s[nt][1];
            sum1 += s[nt][2] + s[nt][3];
        }
        sum0 += __shfl_xor_sync(0xffffffffu, sum0, 1);
        sum0 += __shfl_xor_sync(0xffffffffu, sum0, 2);
        sum1 += __shfl_xor_sync(0xffffffffu, sum1, 1);
        sum1 += __shfl_xor_sync(0xffffffffu, sum1, 2);
        float inv0 = 1.0f / sum0, inv1 = 1.0f / sum1;

        float o[4][4];
        #pragma unroll
        for (int nt = 0; nt < 4; nt++) { o[nt][0]=o[nt][1]=o[nt][2]=o[nt][3]=0.f; }
        int sl = (g << 2) + (q >> 1);
        bool odd = (q & 1);
        #pragma unroll
        for (int kc = 0; kc < 8; kc++) {
            float x0 = __shfl_sync(0xffffffffu, s[kc][0], sl);
            float x1 = __shfl_sync(0xffffffffu, s[kc][1], sl);
            float y0 = __shfl_sync(0xffffffffu, s[kc][2], sl);
            float y1 = __shfl_sync(0xffffffffu, s[kc][3], sl);
            float x2 = __shfl_sync(0xffffffffu, s[kc][0], sl + 2);
            float x3 = __shfl_sync(0xffffffffu, s[kc][1], sl + 2);
            float y2 = __shfl_sync(0xffffffffu, s[kc][2], sl + 2);
            float y3 = __shfl_sync(0xffffffffu, s[kc][3], sl + 2);
            uint32_t pa[4];
            pa[0] = cvt_tf32f(odd ? x1 : x0);
            pa[1] = cvt_tf32f(odd ? y1 : y0);
            pa[2] = cvt_tf32f(odd ? x3 : x2);
            pa[3] = cvt_tf32f(odd ? y3 : y2);
            #pragma unroll
            for (int nt = 0; nt < 4; nt++) {
                int voff0 = (kc*8 + q)*ALSTR + hb + nt*8 + g;
                int voff1 = (kc*8 + q + 4)*ALSTR + hb + nt*8 + g;
                uint32_t b[2];
                b[0] = __float_as_uint(vs[voff0]);
                b[1] = __float_as_uint(vs[voff1]);
                mma_tf32(o[nt], pa, b);
            }
        }
        #pragma unroll
        for (int nt = 0; nt < 4; nt++) {
            int col = hb + nt*8 + 2*q;
            float2 o0 = {o[nt][0]*inv0, o[nt][1]*inv0};
            float2 o1 = {o[nt][2]*inv1, o[nt][3]*inv1};
            *(float2*)(orow + (size_t)(rowbase + g)*CC + col) = o0;
            *(float2*)(orow + (size_t)(rowbase + g + 8)*CC + col) = o1;
        }
    }
}

// ---------------- patch-merge gather + LN over 512 ----------------
__global__ void __launch_bounds__(128) merge_ln_kernel(
    const float* __restrict__ x, const float* __restrict__ g,
    const float* __restrict__ b, float* __restrict__ out)
{
    __shared__ float sred[8];
    int token = blockIdx.x;
    int b_ = token / 2304;
    int ij = token - b_*2304;
    int i2 = ij / 48, j2 = ij - (ij/48)*48;
    int tid = threadIdx.x;
    int warp = tid >> 5, lane = tid & 31;
    int chunk = tid >> 5;
    int cc = (tid & 31) * 4;
    int dh = chunk & 1, dw = chunk >> 1;
    int h = 2*i2 + dh, w = 2*j2 + dw;
    const float* src = x + ((size_t)(b_*(HH*WW) + h*WW + w))*CC + cc;
    float4 v = *(const float4*)src;

    float s = v.x + v.y + v.z + v.w;
    #pragma unroll
    for (int o = 16; o > 0; o >>= 1) s += __shfl_xor_sync(0xffffffffu, s, o);
    if (lane == 0) sred[warp] = s;
    __syncthreads();
    float m = (sred[0]+sred[1]+sred[2]+sred[3]) * (1.0f/512.0f);

    float dx = v.x-m, dy = v.y-m, dz = v.z-m, dwv = v.w-m;
    float q = dx*dx + dy*dy + dz*dz + dwv*dwv;
    #pragma unroll
    for (int o = 16; o > 0; o >>= 1) q += __shfl_xor_sync(0xffffffffu, q, o);
    if (lane == 0) sred[4+warp] = q;
    __syncthreads();
    float var = (sred[4]+sred[5]+sred[6]+sred[7]) * (1.0f/512.0f);
    float inv = rsqrtf(var + 1e-5f);

    int oc = tid*4;
    float4 gg = *(const float4*)(g + oc);
    float4 bb = *(const float4*)(b + oc);
    float4 r;
    r.x = dx*inv*gg.x + bb.x;
    r.y = dy*inv*gg.y + bb.y;
    r.z = dz*inv*gg.z + bb.z;
    r.w = dwv*inv*gg.w + bb.w;
    *(float4*)(out + (size_t)token*512 + oc) = r;
}

// ---------------- host orchestration ----------------
extern "C" void kernel_launch(void* const* d_in, const int* in_sizes, int n_in,
                              void* d_out, int out_size)
{
    (void)in_sizes; (void)n_in; (void)out_size;
    const float* P[28];
    for (int i = 0; i < 28; i++) P[i] = (const float*)d_in[i];
    const float* mln_g = P[25];
    const float* mln_b = P[26];
    const float* red_w = P[27];

    float *px, *pln, *pbig, *pattn, *pxc;
    cudaGetSymbolAddress((void**)&px,   g_x);
    cudaGetSymbolAddress((void**)&pln,  g_ln);
    cudaGetSymbolAddress((void**)&pbig, g_big);
    cudaGetSymbolAddress((void**)&pattn,g_attn);
    cudaGetSymbolAddress((void**)&pxc,  g_xc);

    static int smem_set = 0;
    if (!smem_set) {
        cudaFuncSetAttribute(tgemm<0,128,0>, cudaFuncAttributeMaxDynamicSharedMemorySize, GSMEM);
        cudaFuncSetAttribute(tgemm<1,128,1>, cudaFuncAttributeMaxDynamicSharedMemorySize, GSMEM);
        cudaFuncSetAttribute(tgemm<2,128,0>, cudaFuncAttributeMaxDynamicSharedMemorySize, GSMEM);
        cudaFuncSetAttribute(tgemm<3,512,2>, cudaFuncAttributeMaxDynamicSharedMemorySize, GSMEM);
        cudaFuncSetAttribute(tgemm<3,512,0>, cudaFuncAttributeMaxDynamicSharedMemorySize, GSMEM);
        cudaFuncSetAttribute(tgemm<4,512,0>, cudaFuncAttributeMaxDynamicSharedMemorySize, GSMEM);
        cudaFuncSetAttribute(attn_tc_kernel, cudaFuncAttributeMaxDynamicSharedMemorySize, ASMEM);
        smem_set = 1;
    }

    // ---- block 0 (W-MSA, shift 0) ----
    ln_kernel<<<TT/8, 256>>>((const float*)d_in[0], P[1], P[2], pln, px, 0, 1);
    tgemm<0,128,0><<<dim3(3, TT/128), 256, GSMEM>>>(pln, P[3], P[4], pbig, nullptr, nullptr, nullptr, nullptr, TT, 384, 0);
    attn_tc_kernel<<<WTOT, 256, ASMEM>>>(pbig, pattn, 0);
    tgemm<1,128,1><<<dim3(1, TT/128), 256, GSMEM>>>(pattn, P[5], P[6], px, px, P[7], P[8], pln, TT, 128, 0);
    tgemm<2,128,0><<<dim3(4, TT/128), 256, GSMEM>>>(pln, P[9], P[10], pbig, nullptr, nullptr, nullptr, nullptr, TT, 512, 0);
    tgemm<3,512,2><<<dim3(1, TT/128), 256, GSMEM>>>(pbig, P[11], P[12], px, px, P[13], P[14], pln, TT, 128, 4);

    // ---- block 1 (SW-MSA, shift 4) ----
    tgemm<0,128,0><<<dim3(3, TT/128), 256, GSMEM>>>(pln, P[15], P[16], pbig, nullptr, nullptr, nullptr, nullptr, TT, 384, 0);
    attn_tc_kernel<<<WTOT, 256, ASMEM>>>(pbig, pattn, 1);
    tgemm<1,128,1><<<dim3(1, TT/128), 256, GSMEM>>>(pattn, P[17], P[18], px, px, P[19], P[20], pln, TT, 128, 4);
    tgemm<2,128,0><<<dim3(4, TT/128), 256, GSMEM>>>(pln, P[21], P[22], pbig, nullptr, nullptr, nullptr, nullptr, TT, 512, 0);
    tgemm<3,512,0><<<dim3(1, TT/128), 256, GSMEM>>>(pbig, P[23], P[24], px, px, nullptr, nullptr, nullptr, TT, 128, 0);

    merge_ln_kernel<<<TT/4, 128>>>(px, mln_g, mln_b, pxc);
    tgemm<4,512,0><<<dim3(2, (TT/4)/128), 256, GSMEM>>>(pxc, red_w, nullptr, (float*)d_out, nullptr, nullptr, nullptr, nullptr, TT/4, 256, 0);
}

// round 11
// speedup vs baseline: 1.7220x; 1.0028x over previous
#include <cuda_runtime.h>
#include <cuda_bf16.h>
#include <math.h>
#include <stdint.h>

// ---------------- problem constants ----------------
#define BB   8
#define HH   96
#define WW   96
#define CC   128
#define TT   (BB*HH*WW)      // 73728 tokens
#define NWIN 144             // 12*12 windows per image
#define WTOT (BB*NWIN)       // 1152 windows
#define NTOK 64              // tokens per window

// ---------------- scratch (device globals; no allocation) ----------------
__device__ float g_x[TT*CC];
__device__ float g_ln[TT*CC];
__device__ float g_big[TT*512];
__device__ float g_attn[TT*CC];
__device__ float g_xc[(TT/4)*512];
__device__ float g_wt[524288];        // transposed weights [N][K]

// ---------------- helpers ----------------
__device__ __forceinline__ uint32_t smem_u32(const void* p) {
    uint32_t a;
    asm("{ .reg .u64 t; cvta.to.shared.u64 t, %1; cvt.u32.u64 %0, t; }" : "=r"(a) : "l"(p));
    return a;
}
__device__ __forceinline__ void cp16(uint32_t dst, const void* src) {
    asm volatile("cp.async.cg.shared.global [%0], [%1], 16;" :: "r"(dst), "l"(src));
}
__device__ __forceinline__ void cp_commit() {
    asm volatile("cp.async.commit_group;" ::: "memory");
}
template<int N>
__device__ __forceinline__ void cp_wait() {
    asm volatile("cp.async.wait_group %0;" :: "n"(N) : "memory");
}
__device__ __forceinline__ void mma_tf32(float* c, const uint32_t* a, const uint32_t* b) {
    asm volatile(
        "mma.sync.aligned.m16n8k8.row.col.f32.tf32.tf32.f32 "
        "{%0,%1,%2,%3}, {%4,%5,%6,%7}, {%8,%9}, {%0,%1,%2,%3};"
        : "+f"(c[0]), "+f"(c[1]), "+f"(c[2]), "+f"(c[3])
        : "r"(a[0]), "r"(a[1]), "r"(a[2]), "r"(a[3]), "r"(b[0]), "r"(b[1]));
}
__device__ __forceinline__ void ldsm4(uint32_t* r, uint32_t addr) {
    asm volatile("ldmatrix.sync.aligned.m8n8.x4.shared.b16 {%0,%1,%2,%3}, [%4];"
        : "=r"(r[0]), "=r"(r[1]), "=r"(r[2]), "=r"(r[3]) : "r"(addr));
}
__device__ __forceinline__ uint32_t cvt_tf32f(float x) {
    uint32_t y;
    asm("cvt.rna.tf32.f32 %0, %1;" : "=r"(y) : "f"(x));
    return y;
}

// window-ordered row -> natural token (reverse roll by +shift)
__device__ __forceinline__ int win_to_token(int m, int shift) {
    int b   = m / (NWIN*NTOK);
    int rem = m - b*(NWIN*NTOK);
    int win = rem >> 6;
    int n   = rem & 63;
    int wr = win / 12, wc = win - wr*12;
    int hp = wr*8 + (n >> 3);
    int wp = wc*8 + (n & 7);
    int h = hp + shift; if (h >= HH) h -= HH;
    int w = wp + shift; if (w >= WW) w -= WW;
    return b*(HH*WW) + h*WW + w;
}
// natural token -> window-ordered index
__device__ __forceinline__ int tok_to_win(int t, int shift) {
    int bi = t / (HH*WW);
    int hw = t - bi*(HH*WW);
    int h = hw / WW, w = hw - (hw/WW)*WW;
    int hp = h - shift; if (hp < 0) hp += HH;
    int wp = w - shift; if (wp < 0) wp += WW;
    return bi*(NWIN*NTOK) + ((hp>>3)*12 + (wp>>3))*NTOK + ((hp&7)*8 + (wp&7));
}

// ---------------- weight transpose: out[n][k] = in[k][n] (K,N multiples of 32) ----------------
__global__ void __launch_bounds__(256) wtrans_kernel(
    const float* __restrict__ in, float* __restrict__ outp, int K, int N)
{
    __shared__ float t[32][33];
    int n0 = blockIdx.x*32, k0 = blockIdx.y*32;
    int x = threadIdx.x & 31, y = threadIdx.x >> 5;  // 32 x 8
    #pragma unroll
    for (int i = y; i < 32; i += 8)
        t[i][x] = in[(size_t)(k0+i)*N + n0 + x];
    __syncthreads();
    #pragma unroll
    for (int i = y; i < 32; i += 8)
        outp[(size_t)(n0+i)*K + k0 + x] = t[x][i];
}

// ---------------- LN (warp per token), optional roll+window gather + raw copy ----------------
__global__ void __launch_bounds__(256) ln_kernel(
    const float* __restrict__ x, const float* __restrict__ g,
    const float* __restrict__ b, float* __restrict__ out,
    float* __restrict__ xcopy, int shift, int windowed)
{
    int warp = threadIdx.x >> 5;
    int lane = threadIdx.x & 31;
    int token = blockIdx.x*8 + warp;
    const float4* row = (const float4*)(x + (size_t)token*CC);
    float4 v = row[lane];
    if (xcopy) ((float4*)(xcopy + (size_t)token*CC))[lane] = v;
    float s = v.x + v.y + v.z + v.w;
    #pragma unroll
    for (int o = 16; o > 0; o >>= 1) s += __shfl_xor_sync(0xffffffffu, s, o);
    float m = s * (1.0f/128.0f);
    float dx = v.x - m, dy = v.y - m, dz = v.z - m, dw = v.w - m;
    float q = dx*dx + dy*dy + dz*dz + dw*dw;
    #pragma unroll
    for (int o = 16; o > 0; o >>= 1) q += __shfl_xor_sync(0xffffffffu, q, o);
    float inv = rsqrtf(q * (1.0f/128.0f) + 1e-5f);
    float4 gg = ((const float4*)g)[lane];
    float4 bb = ((const float4*)b)[lane];
    float4 r;
    r.x = dx*inv*gg.x + bb.x;
    r.y = dy*inv*gg.y + bb.y;
    r.z = dz*inv*gg.z + bb.z;
    r.w = dw*inv*gg.w + bb.w;
    int dest = token;
    if (windowed) dest = tok_to_win(token, shift);
    ((float4*)(out + (size_t)dest*CC))[lane] = r;
}

// ---------------- mma.sync tf32 GEMM, BOTH operands via ldmatrix ----------------
// A: [M][K] row-major; BT: [N][K] (pre-transposed weights), both staged as 128x32
// swizzled tiles (128B rows, chunk ^= row&7).
// MODE 0: qkv (+bias, qscale on n0==0, rna output) 1: proj (+bias, scatter+res)
// MODE 2: fc1 (+bias, GELU) 3: fc2 (+bias, res) 4: plain
// LNF: 0 none; 1 also write LN(x); 2 also write LN(x) window-gathered with shift.
#define GBM 128
#define GBN 128
#define GBK 32
#define AFLT (GBM*32)            // 4096 floats = 16KB (A tile == BT tile size)
#define STAGEF (2*AFLT)          // 8192 floats
#define STAGEB (STAGEF*4)        // 32768 bytes
#define NSTAGE 3
#define GSMEM (NSTAGE*STAGEB)    // 98304 bytes

template<int MODE, int K, int LNF>
__global__ void __launch_bounds__(256, 2) tgemm(
    const float* __restrict__ A, const float* __restrict__ BT,
    const float* __restrict__ bias, float* __restrict__ out,
    const float* __restrict__ res,
    const float* __restrict__ lng, const float* __restrict__ lnb,
    float* __restrict__ lnout,
    int M, int N, int shift)
{
    extern __shared__ float sm[];
    uint32_t sb = smem_u32(sm);
    int tid = threadIdx.x;
    int wid = tid >> 5;
    int lane = tid & 31;
    int g = lane >> 2, q = lane & 3;
    int warp_m = wid >> 2, warp_n = wid & 3;
    int m0 = blockIdx.y * GBM, n0 = blockIdx.x * GBN;

    const float* Ab = A + (size_t)m0 * K;
    const float* Bb = BT + (size_t)n0 * K;

    int arow = tid >> 3;                 // 0..31 (+32 per iter)
    int achk = tid & 7;

    int rowlane = lane & 15;
    int hiBit = lane >> 4;
    int lo7 = lane & 7;

    float c[4][4][4];
    #pragma unroll
    for (int mt = 0; mt < 4; mt++)
        #pragma unroll
        for (int nt = 0; nt < 4; nt++)
            #pragma unroll
            for (int i = 0; i < 4; i++) c[mt][nt][i] = 0.0f;

    const int NC = K / GBK;

    auto load_tile = [&](int kb, int buf) {
        uint32_t sA = sb + buf*STAGEB;
        uint32_t sB = sA + AFLT*4;
        const float* Ap = Ab + kb*GBK;
        const float* Bp = Bb + kb*GBK;
        #pragma unroll
        for (int i = 0; i < 4; i++) {
            int r = arow + i*32;
            uint32_t off = (uint32_t)(r*8 + (achk ^ (r & 7)))*16;
            cp16(sA + off, Ap + (size_t)r*K + achk*4);
            cp16(sB + off, Bp + (size_t)r*K + achk*4);
        }
        cp_commit();
    };

    load_tile(0, 0);
    if (NC > 1) load_tile(1, 1);

    int buf = 0;
    #pragma unroll 2
    for (int kb = 0; kb < NC; kb++) {
        if (kb == NC - 1) cp_wait<0>(); else cp_wait<NSTAGE-2>();
        __syncthreads();

        if (kb + 2 < NC) {
            int nbuf = buf + 2; if (nbuf >= NSTAGE) nbuf -= NSTAGE;
            load_tile(kb + 2, nbuf);
        }

        uint32_t aBase = sb + buf*STAGEB + (uint32_t)(warp_m*64 + rowlane)*128;
        uint32_t bBase = sb + buf*STAGEB + AFLT*4 + (uint32_t)(warp_n*32 + rowlane)*128;

        #pragma unroll
        for (int ks = 0; ks < 4; ks++) {
            uint32_t physOff = ((uint32_t)((ks*2 + hiBit) ^ lo7)) << 4;
            uint32_t a[4][4], b[4][2];
            #pragma unroll
            for (int mt = 0; mt < 4; mt++)
                ldsm4(a[mt], aBase + (uint32_t)mt*2048 + physOff);
            #pragma unroll
            for (int ntp = 0; ntp < 2; ntp++) {
                uint32_t bb[4];
                ldsm4(bb, bBase + (uint32_t)ntp*2048 + physOff);
                b[2*ntp+0][0] = bb[0];
                b[2*ntp+1][0] = bb[1];
                b[2*ntp+0][1] = bb[2];
                b[2*ntp+1][1] = bb[3];
            }
            #pragma unroll
            for (int mt = 0; mt < 4; mt++)
                #pragma unroll
                for (int nt = 0; nt < 4; nt++)
                    mma_tf32(c[mt][nt], a[mt], b[nt]);
        }
        buf++; if (buf >= NSTAGE) buf = 0;
    }

    if (LNF == 0) {
        float qscale = (MODE == 0 && n0 == 0) ? 0.17677669529663687f : 1.0f;
        #pragma unroll
        for (int mt = 0; mt < 4; mt++) {
            int r0 = m0 + warp_m*64 + mt*16 + g;
            int r1 = r0 + 8;
            int t0 = r0, t1 = r1;
            if (MODE == 1) { t0 = win_to_token(r0, shift); t1 = win_to_token(r1, shift); }
            #pragma unroll
            for (int nt = 0; nt < 4; nt++) {
                int cb = n0 + warp_n*32 + nt*8 + 2*q;
                float bx = 0.f, by = 0.f;
                if (MODE != 4) { float2 bv = *(const float2*)(bias + cb); bx = bv.x; by = bv.y; }
                float v0 = c[mt][nt][0] + bx, v1 = c[mt][nt][1] + by;
                float v2 = c[mt][nt][2] + bx, v3 = c[mt][nt][3] + by;
                if (MODE == 0) {
                    v0 = __uint_as_float(cvt_tf32f(v0*qscale));
                    v1 = __uint_as_float(cvt_tf32f(v1*qscale));
                    v2 = __uint_as_float(cvt_tf32f(v2*qscale));
                    v3 = __uint_as_float(cvt_tf32f(v3*qscale));
                    float2 o0 = {v0, v1}, o1 = {v2, v3};
                    *(float2*)(out + (size_t)r0*N + cb) = o0;
                    *(float2*)(out + (size_t)r1*N + cb) = o1;
                } else if (MODE == 1) {
                    float2 rv0 = *(const float2*)(res + (size_t)t0*CC + cb);
                    float2 rv1 = *(const float2*)(res + (size_t)t1*CC + cb);
                    float2 o0 = {v0+rv0.x, v1+rv0.y}, o1 = {v2+rv1.x, v3+rv1.y};
                    *(float2*)(out + (size_t)t0*CC + cb) = o0;
                    *(float2*)(out + (size_t)t1*CC + cb) = o1;
                } else if (MODE == 2) {
                    float2 o0, o1;
                    o0.x = 0.5f*v0*(1.0f + erff(v0*0.7071067811865476f));
                    o0.y = 0.5f*v1*(1.0f + erff(v1*0.7071067811865476f));
                    o1.x = 0.5f*v2*(1.0f + erff(v2*0.7071067811865476f));
                    o1.y = 0.5f*v3*(1.0f + erff(v3*0.7071067811865476f));
                    *(float2*)(out + (size_t)r0*N + cb) = o0;
                    *(float2*)(out + (size_t)r1*N + cb) = o1;
                } else if (MODE == 3) {
                    float2 rv0 = *(const float2*)(res + (size_t)r0*N + cb);
                    float2 rv1 = *(const float2*)(res + (size_t)r1*N + cb);
                    float2 o0 = {v0+rv0.x, v1+rv0.y}, o1 = {v2+rv1.x, v3+rv1.y};
                    *(float2*)(out + (size_t)r0*N + cb) = o0;
                    *(float2*)(out + (size_t)r1*N + cb) = o1;
                } else {
                    float2 o0 = {v0, v1}, o1 = {v2, v3};
                    *(float2*)(out + (size_t)r0*N + cb) = o0;
                    *(float2*)(out + (size_t)r1*N + cb) = o1;
                }
            }
        }
    } else {
        // ---- LN-fused epilogue (MODE 1 or 3; N == 128, gridx == 1) ----
        int tok[4][2];
        float rs[4][2], rq[4][2];
        #pragma unroll
        for (int mt = 0; mt < 4; mt++) {
            int r0 = m0 + warp_m*64 + mt*16 + g;
            int r1 = r0 + 8;
            int t0 = (MODE == 1) ? win_to_token(r0, shift) : r0;
            int t1 = (MODE == 1) ? win_to_token(r1, shift) : r1;
            tok[mt][0] = t0; tok[mt][1] = t1;
            float s0 = 0.f, s1 = 0.f, q0 = 0.f, q1 = 0.f;
            #pragma unroll
            for (int nt = 0; nt < 4; nt++) {
                int cb = warp_n*32 + nt*8 + 2*q;
                float2 bv = *(const float2*)(bias + cb);
                float2 rv0 = *(const float2*)(res + (size_t)t0*CC + cb);
                float2 rv1 = *(const float2*)(res + (size_t)t1*CC + cb);
                float v0 = c[mt][nt][0] + bv.x + rv0.x;
                float v1 = c[mt][nt][1] + bv.y + rv0.y;
                float v2 = c[mt][nt][2] + bv.x + rv1.x;
                float v3 = c[mt][nt][3] + bv.y + rv1.y;
                c[mt][nt][0] = v0; c[mt][nt][1] = v1;
                c[mt][nt][2] = v2; c[mt][nt][3] = v3;
                s0 += v0 + v1; q0 += v0*v0 + v1*v1;
                s1 += v2 + v3; q1 += v2*v2 + v3*v3;
            }
            s0 += __shfl_xor_sync(0xffffffffu, s0, 1); s0 += __shfl_xor_sync(0xffffffffu, s0, 2);
            q0 += __shfl_xor_sync(0xffffffffu, q0, 1); q0 += __shfl_xor_sync(0xffffffffu, q0, 2);
            s1 += __shfl_xor_sync(0xffffffffu, s1, 1); s1 += __shfl_xor_sync(0xffffffffu, s1, 2);
            q1 += __shfl_xor_sync(0xffffffffu, q1, 1); q1 += __shfl_xor_sync(0xffffffffu, q1, 2);
            rs[mt][0] = s0; rq[mt][0] = q0;
            rs[mt][1] = s1; rq[mt][1] = q1;
        }
        __syncthreads();
        float* ps = sm;
        float* pq = sm + 512;
        if (q == 0) {
            #pragma unroll
            for (int mt = 0; mt < 4; mt++) {
                int lr0 = warp_m*64 + mt*16 + g;
                ps[warp_n*128 + lr0] = rs[mt][0];
                pq[warp_n*128 + lr0] = rq[mt][0];
                ps[warp_n*128 + lr0 + 8] = rs[mt][1];
                pq[warp_n*128 + lr0 + 8] = rq[mt][1];
            }
        }
        __syncthreads();
        #pragma unroll
        for (int mt = 0; mt < 4; mt++) {
            #pragma unroll
            for (int half = 0; half < 2; half++) {
                int lr = warp_m*64 + mt*16 + g + half*8;
                int t = tok[mt][half];
                float srow = ps[lr] + ps[128 + lr] + ps[256 + lr] + ps[384 + lr];
                float qrow = pq[lr] + pq[128 + lr] + pq[256 + lr] + pq[384 + lr];
                float mean = srow * (1.0f/128.0f);
                float var = qrow * (1.0f/128.0f) - mean*mean;
                float inv = rsqrtf(var + 1e-5f);
                int dest = (LNF == 1) ? t : tok_to_win(t, shift);
                #pragma unroll
                for (int nt = 0; nt < 4; nt++) {
                    int cb = warp_n*32 + nt*8 + 2*q;
                    float v0 = c[mt][nt][half*2+0];
                    float v1 = c[mt][nt][half*2+1];
                    float2 o = {v0, v1};
                    *(float2*)(out + (size_t)t*CC + cb) = o;
                    float2 lg = *(const float2*)(lng + cb);
                    float2 lb = *(const float2*)(lnb + cb);
                    float2 l;
                    l.x = (v0 - mean)*inv*lg.x + lb.x;
                    l.y = (v1 - mean)*inv*lg.y + lb.y;
                    *(float2*)(lnout + (size_t)dest*CC + cb) = l;
                }
            }
        }
    }
}

// ---------------- tensor-core windowed attention (verified layout, raw-bit QKV feed) ----------------
#define ALSTR 132
#define ATILE (64*ALSTR)
#define ASMEM (3*ATILE*4)

__global__ void __launch_bounds__(256) attn_tc_kernel(
    const float* __restrict__ qkv, float* __restrict__ out, int masked)
{
    extern __shared__ float smf[];
    float* qs = smf;
    float* ks = smf + ATILE;
    float* vs = smf + 2*ATILE;

    int tid = threadIdx.x;
    int win = blockIdx.x;
    const float* base = qkv + (size_t)win*NTOK*384;

    for (int i = tid; i < 64*32; i += 256) {
        int r = i >> 5, c4 = (i & 31) * 4;
        const float* rowp = base + (size_t)r*384 + c4;
        *(float4*)(qs + r*ALSTR + c4) = *(const float4*)(rowp);
        *(float4*)(ks + r*ALSTR + c4) = *(const float4*)(rowp + 128);
        *(float4*)(vs + r*ALSTR + c4) = *(const float4*)(rowp + 256);
    }
    __syncthreads();

    int wid = tid >> 5, lane = tid & 31;
    int h = wid >> 1, mhalf = wid & 1;
    int g = lane >> 2, q = lane & 3;
    int hb = h*32;

    int wloc = win % NWIN;
    int wr = wloc / 12, wc = wloc - wr*12;
    bool needmask = masked && (wr == 11 || wc == 11);

    const float NINF = __int_as_float(0xff800000);
    float* orow = out + (size_t)win*NTOK*CC;

    #pragma unroll
    for (int mt = 0; mt < 2; mt++) {
        int rowbase = mhalf*32 + mt*16;
        uint32_t qa[4][4];
        #pragma unroll
        for (int kc = 0; kc < 4; kc++) {
            int off = (rowbase + g)*ALSTR + hb + kc*8 + q;
            qa[kc][0] = __float_as_uint(qs[off]);
            qa[kc][1] = __float_as_uint(qs[off + 8*ALSTR]);
            qa[kc][2] = __float_as_uint(qs[off + 4]);
            qa[kc][3] = __float_as_uint(qs[off + 8*ALSTR + 4]);
        }
        float s[8][4];
        #pragma unroll
        for (int nt = 0; nt < 8; nt++) {
            s[nt][0] = s[nt][1] = s[nt][2] = s[nt][3] = 0.f;
            #pragma unroll
            for (int kc = 0; kc < 4; kc++) {
                int koff = (nt*8 + g)*ALSTR + hb + kc*8 + q;
                uint32_t b[2];
                b[0] = __float_as_uint(ks[koff]);
                b[1] = __float_as_uint(ks[koff + 4]);
                mma_tf32(s[nt], qa[kc], b);
            }
        }
        if (needmask) {
            int t0 = rowbase + g, t1 = t0 + 8;
            int lr0 = ((wr == 11) ? (((t0 >> 3) < 4) ? 1 : 2) : 0)*3 + ((wc == 11) ? (((t0 & 7) < 4) ? 1 : 2) : 0);
            int lr1 = ((wr == 11) ? (((t1 >> 3) < 4) ? 1 : 2) : 0)*3 + ((wc == 11) ? (((t1 & 7) < 4) ? 1 : 2) : 0);
            #pragma unroll
            for (int nt = 0; nt < 8; nt++) {
                int ca = nt*8 + 2*q, cb2 = ca + 1;
                int lca = ((wr == 11) ? ((nt < 4) ? 1 : 2) : 0)*3 + ((wc == 11) ? (((ca & 7) < 4) ? 1 : 2) : 0);
                int lcb = ((wr == 11) ? ((nt < 4) ? 1 : 2) : 0)*3 + ((wc == 11) ? (((cb2 & 7) < 4) ? 1 : 2) : 0);
                if (lca != lr0) s[nt][0] = NINF;
                if (lcb != lr0) s[nt][1] = NINF;
                if (lca != lr1) s[nt][2] = NINF;
                if (lcb != lr1) s[nt][3] = NINF;
            }
        }
        float mx0 = NINF, mx1 = NINF;
        #pragma unroll
        for (int nt = 0; nt < 8; nt++) {
            mx0 = fmaxf(mx0, fmaxf(s[nt][0], s[nt][1]));
            mx1 = fmaxf(mx1, fmaxf(s[nt][2], s[nt][3]));
        }
        mx0 = fmaxf(mx0, __shfl_xor_sync(0xffffffffu, mx0, 1));
        mx0 = fmaxf(mx0, __shfl_xor_sync(0xffffffffu, mx0, 2));
        mx1 = fmaxf(mx1, __shfl_xor_sync(0xffffffffu, mx1, 1));
        mx1 = fmaxf(mx1, __shfl_xor_sync(0xffffffffu, mx1, 2));
        float sum0 = 0.f, sum1 = 0.f;
        #pragma unroll
        for (int nt = 0; nt < 8; nt++) {
            s[nt][0] = __expf(s[nt][0] - mx0);
            s[nt][1] = __expf(s[nt][1] - mx0);
            s[nt][2] = __expf(s[nt][2] - mx1);
            s[nt][3] = __expf(s[nt][3] - mx1);
            sum0 += s[nt][0] + s[nt][1];
            sum1 += s[nt][2] + s[nt][3];
        }
        sum0 += __shfl_xor_sync(0xffffffffu, sum0, 1);
        sum0 += __shfl_xor_sync(0xffffffffu, sum0, 2);
        sum1 += __shfl_xor_sync(0xffffffffu, sum1, 1);
        sum1 += __shfl_xor_sync(0xffffffffu, sum1, 2);
        float inv0 = 1.0f / sum0, inv1 = 1.0f / sum1;

        float o[4][4];
        #pragma unroll
        for (int nt = 0; nt < 4; nt++) { o[nt][0]=o[nt][1]=o[nt][2]=o[nt][3]=0.f; }
        int sl = (g << 2) + (q >> 1);
        bool odd = (q & 1);
        #pragma unroll
        for (int kc = 0; kc < 8; kc++) {
            float x0 = __shfl_sync(0xffffffffu, s[kc][0], sl);
            float x1 = __shfl_sync(0xffffffffu, s[kc][1], sl);
            float y0 = __shfl_sync(0xffffffffu, s[kc][2], sl);
            float y1 = __shfl_sync(0xffffffffu, s[kc][3], sl);
            float x2 = __shfl_sync(0xffffffffu, s[kc][0], sl + 2);
            float x3 = __shfl_sync(0xffffffffu, s[kc][1], sl + 2);
            float y2 = __shfl_sync(0xffffffffu, s[kc][2], sl + 2);
            float y3 = __shfl_sync(0xffffffffu, s[kc][3], sl + 2);
            uint32_t pa[4];
            pa[0] = cvt_tf32f(odd ? x1 : x0);
            pa[1] = cvt_tf32f(odd ? y1 : y0);
            pa[2] = cvt_tf32f(odd ? x3 : x2);
            pa[3] = cvt_tf32f(odd ? y3 : y2);
            #pragma unroll
            for (int nt = 0; nt < 4; nt++) {
                int voff0 = (kc*8 + q)*ALSTR + hb + nt*8 + g;
                int voff1 = (kc*8 + q + 4)*ALSTR + hb + nt*8 + g;
                uint32_t b[2];
                b[0] = __float_as_uint(vs[voff0]);
                b[1] = __float_as_uint(vs[voff1]);
                mma_tf32(o[nt], pa, b);
            }
        }
        #pragma unroll
        for (int nt = 0; nt < 4; nt++) {
            int col = hb + nt*8 + 2*q;
            float2 o0 = {o[nt][0]*inv0, o[nt][1]*inv0};
            float2 o1 = {o[nt][2]*inv1, o[nt][3]*inv1};
            *(float2*)(orow + (size_t)(rowbase + g)*CC + col) = o0;
            *(float2*)(orow + (size_t)(rowbase + g + 8)*CC + col) = o1;
        }
    }
}

// ---------------- patch-merge gather + LN over 512 ----------------
__global__ void __launch_bounds__(128) merge_ln_kernel(
    const float* __restrict__ x, const float* __restrict__ g,
    const float* __restrict__ b, float* __restrict__ out)
{
    __shared__ float sred[8];
    int token = blockIdx.x;
    int b_ = token / 2304;
    int ij = token - b_*2304;
    int i2 = ij / 48, j2 = ij - (ij/48)*48;
    int tid = threadIdx.x;
    int warp = tid >> 5, lane = tid & 31;
    int chunk = tid >> 5;
    int cc = (tid & 31) * 4;
    int dh = chunk & 1, dw = chunk >> 1;
    int h = 2*i2 + dh, w = 2*j2 + dw;
    const float* src = x + ((size_t)(b_*(HH*WW) + h*WW + w))*CC + cc;
    float4 v = *(const float4*)src;

    float s = v.x + v.y + v.z + v.w;
    #pragma unroll
    for (int o = 16; o > 0; o >>= 1) s += __shfl_xor_sync(0xffffffffu, s, o);
    if (lane == 0) sred[warp] = s;
    __syncthreads();
    float m = (sred[0]+sred[1]+sred[2]+sred[3]) * (1.0f/512.0f);

    float dx = v.x-m, dy = v.y-m, dz = v.z-m, dwv = v.w-m;
    float q = dx*dx + dy*dy + dz*dz + dwv*dwv;
    #pragma unroll
    for (int o = 16; o > 0; o >>= 1) q += __shfl_xor_sync(0xffffffffu, q, o);
    if (lane == 0) sred[4+warp] = q;
    __syncthreads();
    float var = (sred[4]+sred[5]+sred[6]+sred[7]) * (1.0f/512.0f);
    float inv = rsqrtf(var + 1e-5f);

    int oc = tid*4;
    float4 gg = *(const float4*)(g + oc);
    float4 bb = *(const float4*)(b + oc);
    float4 r;
    r.x = dx*inv*gg.x + bb.x;
    r.y = dy*inv*gg.y + bb.y;
    r.z = dz*inv*gg.z + bb.z;
    r.w = dwv*inv*gg.w + bb.w;
    *(float4*)(out + (size_t)token*512 + oc) = r;
}

// ---------------- host orchestration ----------------
extern "C" void kernel_launch(void* const* d_in, const int* in_sizes, int n_in,
                              void* d_out, int out_size)
{
    (void)in_sizes; (void)n_in; (void)out_size;
    const float* P[28];
    for (int i = 0; i < 28; i++) P[i] = (const float*)d_in[i];
    const float* mln_g = P[25];
    const float* mln_b = P[26];
    const float* red_w = P[27];

    float *px, *pln, *pbig, *pattn, *pxc, *pwt;
    cudaGetSymbolAddress((void**)&px,   g_x);
    cudaGetSymbolAddress((void**)&pln,  g_ln);
    cudaGetSymbolAddress((void**)&pbig, g_big);
    cudaGetSymbolAddress((void**)&pattn,g_attn);
    cudaGetSymbolAddress((void**)&pxc,  g_xc);
    cudaGetSymbolAddress((void**)&pwt,  g_wt);

    static int smem_set = 0;
    if (!smem_set) {
        cudaFuncSetAttribute(tgemm<0,128,0>, cudaFuncAttributeMaxDynamicSharedMemorySize, GSMEM);
        cudaFuncSetAttribute(tgemm<1,128,1>, cudaFuncAttributeMaxDynamicSharedMemorySize, GSMEM);
        cudaFuncSetAttribute(tgemm<2,128,0>, cudaFuncAttributeMaxDynamicSharedMemorySize, GSMEM);
        cudaFuncSetAttribute(tgemm<3,512,2>, cudaFuncAttributeMaxDynamicSharedMemorySize, GSMEM);
        cudaFuncSetAttribute(tgemm<3,512,0>, cudaFuncAttributeMaxDynamicSharedMemorySize, GSMEM);
        cudaFuncSetAttribute(tgemm<4,512,0>, cudaFuncAttributeMaxDynamicSharedMemorySize, GSMEM);
        cudaFuncSetAttribute(attn_tc_kernel, cudaFuncAttributeMaxDynamicSharedMemorySize, ASMEM);
        smem_set = 1;
    }

    // ---- transpose all weights into g_wt as [N][K] ----
    // per block: qkvT(49152) projT(16384) fc1T(65536) fc2T(65536); red at 393216
    for (int blk = 0; blk < 2; blk++) {
        int base = 1 + blk*12;
        float* o = pwt + blk*196608;
        wtrans_kernel<<<dim3(384/32, 128/32), 256>>>(P[base+2],  o,        128, 384);
        wtrans_kernel<<<dim3(128/32, 128/32), 256>>>(P[base+4],  o+49152,  128, 128);
        wtrans_kernel<<<dim3(512/32, 128/32), 256>>>(P[base+8],  o+65536,  128, 512);
        wtrans_kernel<<<dim3(128/32, 512/32), 256>>>(P[base+10], o+131072, 512, 128);
    }
    wtrans_kernel<<<dim3(256/32, 512/32), 256>>>(red_w, pwt+393216, 512, 256);

    // ---- block 0 (W-MSA, shift 0) ----
    ln_kernel<<<TT/8, 256>>>((const float*)d_in[0], P[1], P[2], pln, px, 0, 1);
    tgemm<0,128,0><<<dim3(3, TT/128), 256, GSMEM>>>(pln, pwt, P[4], pbig, nullptr, nullptr, nullptr, nullptr, TT, 384, 0);
    attn_tc_kernel<<<WTOT, 256, ASMEM>>>(pbig, pattn, 0);
    tgemm<1,128,1><<<dim3(1, TT/128), 256, GSMEM>>>(pattn, pwt+49152, P[6], px, px, P[7], P[8], pln, TT, 128, 0);
    tgemm<2,128,0><<<dim3(4, TT/128), 256, GSMEM>>>(pln, pwt+65536, P[10], pbig, nullptr, nullptr, nullptr, nullptr, TT, 512, 0);
    tgemm<3,512,2><<<dim3(1, TT/128), 256, GSMEM>>>(pbig, pwt+131072, P[12], px, px, P[13], P[14], pln, TT, 128, 4);

    // ---- block 1 (SW-MSA, shift 4) ----
    tgemm<0,128,0><<<dim3(3, TT/128), 256, GSMEM>>>(pln, pwt+196608, P[16], pbig, nullptr, nullptr, nullptr, nullptr, TT, 384, 0);
    attn_tc_kernel<<<WTOT, 256, ASMEM>>>(pbig, pattn, 1);
    tgemm<1,128,1><<<dim3(1, TT/128), 256, GSMEM>>>(pattn, pwt+196608+49152, P[18], px, px, P[19], P[20], pln, TT, 128, 4);
    tgemm<2,128,0><<<dim3(4, TT/128), 256, GSMEM>>>(pln, pwt+196608+65536, P[22], pbig, nullptr, nullptr, nullptr, nullptr, TT, 512, 0);
    tgemm<3,512,0><<<dim3(1, TT/128), 256, GSMEM>>>(pbig, pwt+196608+131072, P[24], px, px, nullptr, nullptr, nullptr, TT, 128, 0);

    merge_ln_kernel<<<TT/4, 128>>>(px, mln_g, mln_b, pxc);
    tgemm<4,512,0><<<dim3(2, (TT/4)/128), 256, GSMEM>>>(pxc, pwt+393216, nullptr, (float*)d_out, nullptr, nullptr, nullptr, nullptr, TT/4, 256, 0);
}

// round 12
// speedup vs baseline: 1.7297x; 1.0045x over previous
#include <cuda_runtime.h>
#include <cuda_bf16.h>
#include <math.h>
#include <stdint.h>

// ---------------- problem constants ----------------
#define BB   8
#define HH   96
#define WW   96
#define CC   128
#define TT   (BB*HH*WW)      // 73728 tokens
#define NWIN 144             // 12*12 windows per image
#define WTOT (BB*NWIN)       // 1152 windows
#define NTOK 64              // tokens per window

// ---------------- scratch (device globals; no allocation) ----------------
__device__ float g_x[TT*CC];
__device__ float g_ln[TT*CC];
__device__ float g_big[TT*512];
__device__ float g_attn[TT*CC];
__device__ float g_xc[(TT/4)*512];
__device__ float g_wt[524288];        // transposed weights [N][K]

// ---------------- helpers ----------------
__device__ __forceinline__ uint32_t smem_u32(const void* p) {
    uint32_t a;
    asm("{ .reg .u64 t; cvta.to.shared.u64 t, %1; cvt.u32.u64 %0, t; }" : "=r"(a) : "l"(p));
    return a;
}
__device__ __forceinline__ void cp16(uint32_t dst, const void* src) {
    asm volatile("cp.async.cg.shared.global [%0], [%1], 16;" :: "r"(dst), "l"(src));
}
__device__ __forceinline__ void cp_commit() {
    asm volatile("cp.async.commit_group;" ::: "memory");
}
template<int N>
__device__ __forceinline__ void cp_wait() {
    asm volatile("cp.async.wait_group %0;" :: "n"(N) : "memory");
}
__device__ __forceinline__ void mma_tf32(float* c, const uint32_t* a, const uint32_t* b) {
    asm volatile(
        "mma.sync.aligned.m16n8k8.row.col.f32.tf32.tf32.f32 "
        "{%0,%1,%2,%3}, {%4,%5,%6,%7}, {%8,%9}, {%0,%1,%2,%3};"
        : "+f"(c[0]), "+f"(c[1]), "+f"(c[2]), "+f"(c[3])
        : "r"(a[0]), "r"(a[1]), "r"(a[2]), "r"(a[3]), "r"(b[0]), "r"(b[1]));
}
__device__ __forceinline__ void ldsm4(uint32_t* r, uint32_t addr) {
    asm volatile("ldmatrix.sync.aligned.m8n8.x4.shared.b16 {%0,%1,%2,%3}, [%4];"
        : "=r"(r[0]), "=r"(r[1]), "=r"(r[2]), "=r"(r[3]) : "r"(addr));
}
__device__ __forceinline__ uint32_t cvt_tf32f(float x) {
    uint32_t y;
    asm("cvt.rna.tf32.f32 %0, %1;" : "=r"(y) : "f"(x));
    return y;
}

// window-ordered row -> natural token (reverse roll by +shift)
__device__ __forceinline__ int win_to_token(int m, int shift) {
    int b   = m / (NWIN*NTOK);
    int rem = m - b*(NWIN*NTOK);
    int win = rem >> 6;
    int n   = rem & 63;
    int wr = win / 12, wc = win - wr*12;
    int hp = wr*8 + (n >> 3);
    int wp = wc*8 + (n & 7);
    int h = hp + shift; if (h >= HH) h -= HH;
    int w = wp + shift; if (w >= WW) w -= WW;
    return b*(HH*WW) + h*WW + w;
}
// natural token -> window-ordered index
__device__ __forceinline__ int tok_to_win(int t, int shift) {
    int bi = t / (HH*WW);
    int hw = t - bi*(HH*WW);
    int h = hw / WW, w = hw - (hw/WW)*WW;
    int hp = h - shift; if (hp < 0) hp += HH;
    int wp = w - shift; if (wp < 0) wp += WW;
    return bi*(NWIN*NTOK) + ((hp>>3)*12 + (wp>>3))*NTOK + ((hp&7)*8 + (wp&7));
}

// ---------------- ALL weight transposes in one launch ----------------
// g_wt layout: blk0 {qkvT@0(N384K128) projT@49152(128,128) fc1T@65536(N512K128)
// fc2T@131072(N128K512)} blk1 same +196608; redT@393216(N256K512)
__global__ void __launch_bounds__(256) wtrans_all_kernel(
    const float* __restrict__ qkv0, const float* __restrict__ proj0,
    const float* __restrict__ fc10, const float* __restrict__ fc20,
    const float* __restrict__ qkv1, const float* __restrict__ proj1,
    const float* __restrict__ fc11, const float* __restrict__ fc21,
    const float* __restrict__ red,  float* __restrict__ wt)
{
    __shared__ float t[32][33];
    int tb = blockIdx.x;
    const float* in; int K, N, ntn, off;
    if      (tb < 48)  {            in = qkv0;  K=128; N=384; ntn=12; off=0; }
    else if (tb < 64)  { tb -= 48;  in = proj0; K=128; N=128; ntn=4;  off=49152; }
    else if (tb < 128) { tb -= 64;  in = fc10;  K=128; N=512; ntn=16; off=65536; }
    else if (tb < 192) { tb -= 128; in = fc20;  K=512; N=128; ntn=4;  off=131072; }
    else if (tb < 240) { tb -= 192; in = qkv1;  K=128; N=384; ntn=12; off=196608; }
    else if (tb < 256) { tb -= 240; in = proj1; K=128; N=128; ntn=4;  off=196608+49152; }
    else if (tb < 320) { tb -= 256; in = fc11;  K=128; N=512; ntn=16; off=196608+65536; }
    else if (tb < 384) { tb -= 320; in = fc21;  K=512; N=128; ntn=4;  off=196608+131072; }
    else               { tb -= 384; in = red;   K=512; N=256; ntn=8;  off=393216; }
    int n0 = (tb % ntn)*32, k0 = (tb / ntn)*32;
    float* outp = wt + off;
    int x = threadIdx.x & 31, y = threadIdx.x >> 5;  // 32 x 8
    #pragma unroll
    for (int i = y; i < 32; i += 8)
        t[i][x] = in[(size_t)(k0+i)*N + n0 + x];
    __syncthreads();
    #pragma unroll
    for (int i = y; i < 32; i += 8)
        outp[(size_t)(n0+i)*K + k0 + x] = t[x][i];
}

// ---------------- LN (warp per token), optional roll+window gather + raw copy ----------------
__global__ void __launch_bounds__(256) ln_kernel(
    const float* __restrict__ x, const float* __restrict__ g,
    const float* __restrict__ b, float* __restrict__ out,
    float* __restrict__ xcopy, int shift, int windowed)
{
    int warp = threadIdx.x >> 5;
    int lane = threadIdx.x & 31;
    int token = blockIdx.x*8 + warp;
    const float4* row = (const float4*)(x + (size_t)token*CC);
    float4 v = row[lane];
    if (xcopy) ((float4*)(xcopy + (size_t)token*CC))[lane] = v;
    float s = v.x + v.y + v.z + v.w;
    #pragma unroll
    for (int o = 16; o > 0; o >>= 1) s += __shfl_xor_sync(0xffffffffu, s, o);
    float m = s * (1.0f/128.0f);
    float dx = v.x - m, dy = v.y - m, dz = v.z - m, dw = v.w - m;
    float q = dx*dx + dy*dy + dz*dz + dw*dw;
    #pragma unroll
    for (int o = 16; o > 0; o >>= 1) q += __shfl_xor_sync(0xffffffffu, q, o);
    float inv = rsqrtf(q * (1.0f/128.0f) + 1e-5f);
    float4 gg = ((const float4*)g)[lane];
    float4 bb = ((const float4*)b)[lane];
    float4 r;
    r.x = dx*inv*gg.x + bb.x;
    r.y = dy*inv*gg.y + bb.y;
    r.z = dz*inv*gg.z + bb.z;
    r.w = dw*inv*gg.w + bb.w;
    int dest = token;
    if (windowed) dest = tok_to_win(token, shift);
    ((float4*)(out + (size_t)dest*CC))[lane] = r;
}

// ---------------- mma.sync tf32 GEMM, BOTH operands via ldmatrix ----------------
#define GBM 128
#define GBN 128
#define GBK 32
#define AFLT (GBM*32)
#define STAGEF (2*AFLT)
#define STAGEB (STAGEF*4)
#define NSTAGE 3
#define GSMEM (NSTAGE*STAGEB)

template<int MODE, int K, int LNF>
__global__ void __launch_bounds__(256, 2) tgemm(
    const float* __restrict__ A, const float* __restrict__ BT,
    const float* __restrict__ bias, float* __restrict__ out,
    const float* __restrict__ res,
    const float* __restrict__ lng, const float* __restrict__ lnb,
    float* __restrict__ lnout,
    int M, int N, int shift)
{
    extern __shared__ float sm[];
    uint32_t sb = smem_u32(sm);
    int tid = threadIdx.x;
    int wid = tid >> 5;
    int lane = tid & 31;
    int g = lane >> 2, q = lane & 3;
    int warp_m = wid >> 2, warp_n = wid & 3;
    int m0 = blockIdx.y * GBM, n0 = blockIdx.x * GBN;

    const float* Ab = A + (size_t)m0 * K;
    const float* Bb = BT + (size_t)n0 * K;

    int arow = tid >> 3;
    int achk = tid & 7;

    int rowlane = lane & 15;
    int hiBit = lane >> 4;
    int lo7 = lane & 7;

    float c[4][4][4];
    #pragma unroll
    for (int mt = 0; mt < 4; mt++)
        #pragma unroll
        for (int nt = 0; nt < 4; nt++)
            #pragma unroll
            for (int i = 0; i < 4; i++) c[mt][nt][i] = 0.0f;

    const int NC = K / GBK;

    auto load_tile = [&](int kb, int buf) {
        uint32_t sA = sb + buf*STAGEB;
        uint32_t sB = sA + AFLT*4;
        const float* Ap = Ab + kb*GBK;
        const float* Bp = Bb + kb*GBK;
        #pragma unroll
        for (int i = 0; i < 4; i++) {
            int r = arow + i*32;
            uint32_t off = (uint32_t)(r*8 + (achk ^ (r & 7)))*16;
            cp16(sA + off, Ap + (size_t)r*K + achk*4);
            cp16(sB + off, Bp + (size_t)r*K + achk*4);
        }
        cp_commit();
    };

    load_tile(0, 0);
    if (NC > 1) load_tile(1, 1);

    int buf = 0;
    #pragma unroll 2
    for (int kb = 0; kb < NC; kb++) {
        if (kb == NC - 1) cp_wait<0>(); else cp_wait<NSTAGE-2>();
        __syncthreads();

        if (kb + 2 < NC) {
            int nbuf = buf + 2; if (nbuf >= NSTAGE) nbuf -= NSTAGE;
            load_tile(kb + 2, nbuf);
        }

        uint32_t aBase = sb + buf*STAGEB + (uint32_t)(warp_m*64 + rowlane)*128;
        uint32_t bBase = sb + buf*STAGEB + AFLT*4 + (uint32_t)(warp_n*32 + rowlane)*128;

        #pragma unroll
        for (int ks = 0; ks < 4; ks++) {
            uint32_t physOff = ((uint32_t)((ks*2 + hiBit) ^ lo7)) << 4;
            uint32_t a[4][4], b[4][2];
            #pragma unroll
            for (int mt = 0; mt < 4; mt++)
                ldsm4(a[mt], aBase + (uint32_t)mt*2048 + physOff);
            #pragma unroll
            for (int ntp = 0; ntp < 2; ntp++) {
                uint32_t bb[4];
                ldsm4(bb, bBase + (uint32_t)ntp*2048 + physOff);
                b[2*ntp+0][0] = bb[0];
                b[2*ntp+1][0] = bb[1];
                b[2*ntp+0][1] = bb[2];
                b[2*ntp+1][1] = bb[3];
            }
            #pragma unroll
            for (int mt = 0; mt < 4; mt++)
                #pragma unroll
                for (int nt = 0; nt < 4; nt++)
                    mma_tf32(c[mt][nt], a[mt], b[nt]);
        }
        buf++; if (buf >= NSTAGE) buf = 0;
    }

    if (LNF == 0) {
        float qscale = (MODE == 0 && n0 == 0) ? 0.17677669529663687f : 1.0f;
        #pragma unroll
        for (int mt = 0; mt < 4; mt++) {
            int r0 = m0 + warp_m*64 + mt*16 + g;
            int r1 = r0 + 8;
            int t0 = r0, t1 = r1;
            if (MODE == 1) { t0 = win_to_token(r0, shift); t1 = win_to_token(r1, shift); }
            #pragma unroll
            for (int nt = 0; nt < 4; nt++) {
                int cb = n0 + warp_n*32 + nt*8 + 2*q;
                float bx = 0.f, by = 0.f;
                if (MODE != 4) { float2 bv = *(const float2*)(bias + cb); bx = bv.x; by = bv.y; }
                float v0 = c[mt][nt][0] + bx, v1 = c[mt][nt][1] + by;
                float v2 = c[mt][nt][2] + bx, v3 = c[mt][nt][3] + by;
                if (MODE == 0) {
                    v0 = __uint_as_float(cvt_tf32f(v0*qscale));
                    v1 = __uint_as_float(cvt_tf32f(v1*qscale));
                    v2 = __uint_as_float(cvt_tf32f(v2*qscale));
                    v3 = __uint_as_float(cvt_tf32f(v3*qscale));
                    float2 o0 = {v0, v1}, o1 = {v2, v3};
                    *(float2*)(out + (size_t)r0*N + cb) = o0;
                    *(float2*)(out + (size_t)r1*N + cb) = o1;
                } else if (MODE == 1) {
                    float2 rv0 = *(const float2*)(res + (size_t)t0*CC + cb);
                    float2 rv1 = *(const float2*)(res + (size_t)t1*CC + cb);
                    float2 o0 = {v0+rv0.x, v1+rv0.y}, o1 = {v2+rv1.x, v3+rv1.y};
                    *(float2*)(out + (size_t)t0*CC + cb) = o0;
                    *(float2*)(out + (size_t)t1*CC + cb) = o1;
                } else if (MODE == 2) {
                    float2 o0, o1;
                    o0.x = 0.5f*v0*(1.0f + erff(v0*0.7071067811865476f));
                    o0.y = 0.5f*v1*(1.0f + erff(v1*0.7071067811865476f));
                    o1.x = 0.5f*v2*(1.0f + erff(v2*0.7071067811865476f));
                    o1.y = 0.5f*v3*(1.0f + erff(v3*0.7071067811865476f));
                    *(float2*)(out + (size_t)r0*N + cb) = o0;
                    *(float2*)(out + (size_t)r1*N + cb) = o1;
                } else if (MODE == 3) {
                    float2 rv0 = *(const float2*)(res + (size_t)r0*N + cb);
                    float2 rv1 = *(const float2*)(res + (size_t)r1*N + cb);
                    float2 o0 = {v0+rv0.x, v1+rv0.y}, o1 = {v2+rv1.x, v3+rv1.y};
                    *(float2*)(out + (size_t)r0*N + cb) = o0;
                    *(float2*)(out + (size_t)r1*N + cb) = o1;
                } else {
                    float2 o0 = {v0, v1}, o1 = {v2, v3};
                    *(float2*)(out + (size_t)r0*N + cb) = o0;
                    *(float2*)(out + (size_t)r1*N + cb) = o1;
                }
            }
        }
    } else {
        // ---- LN-fused epilogue (MODE 1 or 3; N == 128, gridx == 1) ----
        int tok[4][2];
        float rs[4][2], rq[4][2];
        #pragma unroll
        for (int mt = 0; mt < 4; mt++) {
            int r0 = m0 + warp_m*64 + mt*16 + g;
            int r1 = r0 + 8;
            int t0 = (MODE == 1) ? win_to_token(r0, shift) : r0;
            int t1 = (MODE == 1) ? win_to_token(r1, shift) : r1;
            tok[mt][0] = t0; tok[mt][1] = t1;
            float s0 = 0.f, s1 = 0.f, q0 = 0.f, q1 = 0.f;
            #pragma unroll
            for (int nt = 0; nt < 4; nt++) {
                int cb = warp_n*32 + nt*8 + 2*q;
                float2 bv = *(const float2*)(bias + cb);
                float2 rv0 = *(const float2*)(res + (size_t)t0*CC + cb);
                float2 rv1 = *(const float2*)(res + (size_t)t1*CC + cb);
                float v0 = c[mt][nt][0] + bv.x + rv0.x;
                float v1 = c[mt][nt][1] + bv.y + rv0.y;
                float v2 = c[mt][nt][2] + bv.x + rv1.x;
                float v3 = c[mt][nt][3] + bv.y + rv1.y;
                c[mt][nt][0] = v0; c[mt][nt][1] = v1;
                c[mt][nt][2] = v2; c[mt][nt][3] = v3;
                s0 += v0 + v1; q0 += v0*v0 + v1*v1;
                s1 += v2 + v3; q1 += v2*v2 + v3*v3;
            }
            s0 += __shfl_xor_sync(0xffffffffu, s0, 1); s0 += __shfl_xor_sync(0xffffffffu, s0, 2);
            q0 += __shfl_xor_sync(0xffffffffu, q0, 1); q0 += __shfl_xor_sync(0xffffffffu, q0, 2);
            s1 += __shfl_xor_sync(0xffffffffu, s1, 1); s1 += __shfl_xor_sync(0xffffffffu, s1, 2);
            q1 += __shfl_xor_sync(0xffffffffu, q1, 1); q1 += __shfl_xor_sync(0xffffffffu, q1, 2);
            rs[mt][0] = s0; rq[mt][0] = q0;
            rs[mt][1] = s1; rq[mt][1] = q1;
        }
        __syncthreads();
        float* ps = sm;
        float* pq = sm + 512;
        if (q == 0) {
            #pragma unroll
            for (int mt = 0; mt < 4; mt++) {
                int lr0 = warp_m*64 + mt*16 + g;
                ps[warp_n*128 + lr0] = rs[mt][0];
                pq[warp_n*128 + lr0] = rq[mt][0];
                ps[warp_n*128 + lr0 + 8] = rs[mt][1];
                pq[warp_n*128 + lr0 + 8] = rq[mt][1];
            }
        }
        __syncthreads();
        #pragma unroll
        for (int mt = 0; mt < 4; mt++) {
            #pragma unroll
            for (int half = 0; half < 2; half++) {
                int lr = warp_m*64 + mt*16 + g + half*8;
                int t = tok[mt][half];
                float srow = ps[lr] + ps[128 + lr] + ps[256 + lr] + ps[384 + lr];
                float qrow = pq[lr] + pq[128 + lr] + pq[256 + lr] + pq[384 + lr];
                float mean = srow * (1.0f/128.0f);
                float var = qrow * (1.0f/128.0f) - mean*mean;
                float inv = rsqrtf(var + 1e-5f);
                int dest = (LNF == 1) ? t : tok_to_win(t, shift);
                #pragma unroll
                for (int nt = 0; nt < 4; nt++) {
                    int cb = warp_n*32 + nt*8 + 2*q;
                    float v0 = c[mt][nt][half*2+0];
                    float v1 = c[mt][nt][half*2+1];
                    float2 o = {v0, v1};
                    *(float2*)(out + (size_t)t*CC + cb) = o;
                    float2 lg = *(const float2*)(lng + cb);
                    float2 lb = *(const float2*)(lnb + cb);
                    float2 l;
                    l.x = (v0 - mean)*inv*lg.x + lb.x;
                    l.y = (v1 - mean)*inv*lg.y + lb.y;
                    *(float2*)(lnout + (size_t)dest*CC + cb) = l;
                }
            }
        }
    }
}

// ---------------- tensor-core windowed attention, 2-buffer staging (3 CTAs/SM) ----------------
#define ALSTR 132
#define ATILE (64*ALSTR)
#define ASMEM (2*ATILE*4)       // 67584 bytes

__global__ void __launch_bounds__(256, 3) attn_tc_kernel(
    const float* __restrict__ qkv, float* __restrict__ out, int masked)
{
    extern __shared__ float smf[];
    float* ks = smf;
    float* vs = smf + ATILE;

    int tid = threadIdx.x;
    int win = blockIdx.x;
    const float* base = qkv + (size_t)win*NTOK*384;

    int wid = tid >> 5, lane = tid & 31;
    int h = wid >> 1, mhalf = wid & 1;
    int g = lane >> 2, q = lane & 3;
    int hb = h*32;

    // ---- phase 1: stage Q into ks buffer, grab fragments for BOTH m-tiles ----
    for (int i = tid; i < 64*32; i += 256) {
        int r = i >> 5, c4 = (i & 31) * 4;
        *(float4*)(ks + r*ALSTR + c4) = *(const float4*)(base + (size_t)r*384 + c4);
    }
    __syncthreads();
    uint32_t qa2[2][4][4];
    #pragma unroll
    for (int mt = 0; mt < 2; mt++) {
        int rowbase = mhalf*32 + mt*16;
        #pragma unroll
        for (int kc = 0; kc < 4; kc++) {
            int off = (rowbase + g)*ALSTR + hb + kc*8 + q;
            qa2[mt][kc][0] = __float_as_uint(ks[off]);
            qa2[mt][kc][1] = __float_as_uint(ks[off + 8*ALSTR]);
            qa2[mt][kc][2] = __float_as_uint(ks[off + 4]);
            qa2[mt][kc][3] = __float_as_uint(ks[off + 8*ALSTR + 4]);
        }
    }
    __syncthreads();
    // ---- phase 2: stage K and V ----
    for (int i = tid; i < 64*32; i += 256) {
        int r = i >> 5, c4 = (i & 31) * 4;
        const float* rowp = base + (size_t)r*384 + c4;
        *(float4*)(ks + r*ALSTR + c4) = *(const float4*)(rowp + 128);
        *(float4*)(vs + r*ALSTR + c4) = *(const float4*)(rowp + 256);
    }
    __syncthreads();

    int wloc = win % NWIN;
    int wr = wloc / 12, wc = wloc - wr*12;
    bool needmask = masked && (wr == 11 || wc == 11);

    const float NINF = __int_as_float(0xff800000);
    float* orow = out + (size_t)win*NTOK*CC;

    #pragma unroll
    for (int mt = 0; mt < 2; mt++) {
        int rowbase = mhalf*32 + mt*16;
        float s[8][4];
        #pragma unroll
        for (int nt = 0; nt < 8; nt++) {
            s[nt][0] = s[nt][1] = s[nt][2] = s[nt][3] = 0.f;
            #pragma unroll
            for (int kc = 0; kc < 4; kc++) {
                int koff = (nt*8 + g)*ALSTR + hb + kc*8 + q;
                uint32_t b[2];
                b[0] = __float_as_uint(ks[koff]);
                b[1] = __float_as_uint(ks[koff + 4]);
                mma_tf32(s[nt], qa2[mt][kc], b);
            }
        }
        if (needmask) {
            int t0 = rowbase + g, t1 = t0 + 8;
            int lr0 = ((wr == 11) ? (((t0 >> 3) < 4) ? 1 : 2) : 0)*3 + ((wc == 11) ? (((t0 & 7) < 4) ? 1 : 2) : 0);
            int lr1 = ((wr == 11) ? (((t1 >> 3) < 4) ? 1 : 2) : 0)*3 + ((wc == 11) ? (((t1 & 7) < 4) ? 1 : 2) : 0);
            #pragma unroll
            for (int nt = 0; nt < 8; nt++) {
                int ca = nt*8 + 2*q, cb2 = ca + 1;
                int lca = ((wr == 11) ? ((nt < 4) ? 1 : 2) : 0)*3 + ((wc == 11) ? (((ca & 7) < 4) ? 1 : 2) : 0);
                int lcb = ((wr == 11) ? ((nt < 4) ? 1 : 2) : 0)*3 + ((wc == 11) ? (((cb2 & 7) < 4) ? 1 : 2) : 0);
                if (lca != lr0) s[nt][0] = NINF;
                if (lcb != lr0) s[nt][1] = NINF;
                if (lca != lr1) s[nt][2] = NINF;
                if (lcb != lr1) s[nt][3] = NINF;
            }
        }
        float mx0 = NINF, mx1 = NINF;
        #pragma unroll
        for (int nt = 0; nt < 8; nt++) {
            mx0 = fmaxf(mx0, fmaxf(s[nt][0], s[nt][1]));
            mx1 = fmaxf(mx1, fmaxf(s[nt][2], s[nt][3]));
        }
        mx0 = fmaxf(mx0, __shfl_xor_sync(0xffffffffu, mx0, 1));
        mx0 = fmaxf(mx0, __shfl_xor_sync(0xffffffffu, mx0, 2));
        mx1 = fmaxf(mx1, __shfl_xor_sync(0xffffffffu, mx1, 1));
        mx1 = fmaxf(mx1, __shfl_xor_sync(0xffffffffu, mx1, 2));
        float sum0 = 0.f, sum1 = 0.f;
        #pragma unroll
        for (int nt = 0; nt < 8; nt++) {
            s[nt][0] = __expf(s[nt][0] - mx0);
            s[nt][1] = __expf(s[nt][1] - mx0);
            s[nt][2] = __expf(s[nt][2] - mx1);
            s[nt][3] = __expf(s[nt][3] - mx1);
            sum0 += s[nt][0] + s[nt][1];
            sum1 += s[nt][2] + s[nt][3];
        }
        sum0 += __shfl_xor_sync(0xffffffffu, sum0, 1);
        sum0 += __shfl_xor_sync(0xffffffffu, sum0, 2);
        sum1 += __shfl_xor_sync(0xffffffffu, sum1, 1);
        sum1 += __shfl_xor_sync(0xffffffffu, sum1, 2);
        float inv0 = 1.0f / sum0, inv1 = 1.0f / sum1;

        float o[4][4];
        #pragma unroll
        for (int nt = 0; nt < 4; nt++) { o[nt][0]=o[nt][1]=o[nt][2]=o[nt][3]=0.f; }
        int sl = (g << 2) + (q >> 1);
        bool odd = (q & 1);
        #pragma unroll
        for (int kc = 0; kc < 8; kc++) {
            float x0 = __shfl_sync(0xffffffffu, s[kc][0], sl);
            float x1 = __shfl_sync(0xffffffffu, s[kc][1], sl);
            float y0 = __shfl_sync(0xffffffffu, s[kc][2], sl);
            float y1 = __shfl_sync(0xffffffffu, s[kc][3], sl);
            float x2 = __shfl_sync(0xffffffffu, s[kc][0], sl + 2);
            float x3 = __shfl_sync(0xffffffffu, s[kc][1], sl + 2);
            float y2 = __shfl_sync(0xffffffffu, s[kc][2], sl + 2);
            float y3 = __shfl_sync(0xffffffffu, s[kc][3], sl + 2);
            uint32_t pa[4];
            pa[0] = cvt_tf32f(odd ? x1 : x0);
            pa[1] = cvt_tf32f(odd ? y1 : y0);
            pa[2] = cvt_tf32f(odd ? x3 : x2);
            pa[3] = cvt_tf32f(odd ? y3 : y2);
            #pragma unroll
            for (int nt = 0; nt < 4; nt++) {
                int voff0 = (kc*8 + q)*ALSTR + hb + nt*8 + g;
                int voff1 = (kc*8 + q + 4)*ALSTR + hb + nt*8 + g;
                uint32_t b[2];
                b[0] = __float_as_uint(vs[voff0]);
                b[1] = __float_as_uint(vs[voff1]);
                mma_tf32(o[nt], pa, b);
            }
        }
        #pragma unroll
        for (int nt = 0; nt < 4; nt++) {
            int col = hb + nt*8 + 2*q;
            float2 o0 = {o[nt][0]*inv0, o[nt][1]*inv0};
            float2 o1 = {o[nt][2]*inv1, o[nt][3]*inv1};
            *(float2*)(orow + (size_t)(rowbase + g)*CC + col) = o0;
            *(float2*)(orow + (size_t)(rowbase + g + 8)*CC + col) = o1;
        }
    }
}

// ---------------- patch-merge gather + LN over 512 ----------------
__global__ void __launch_bounds__(128) merge_ln_kernel(
    const float* __restrict__ x, const float* __restrict__ g,
    const float* __restrict__ b, float* __restrict__ out)
{
    __shared__ float sred[8];
    int token = blockIdx.x;
    int b_ = token / 2304;
    int ij = token - b_*2304;
    int i2 = ij / 48, j2 = ij - (ij/48)*48;
    int tid = threadIdx.x;
    int warp = tid >> 5, lane = tid & 31;
    int chunk = tid >> 5;
    int cc = (tid & 31) * 4;
    int dh = chunk & 1, dw = chunk >> 1;
    int h = 2*i2 + dh, w = 2*j2 + dw;
    const float* src = x + ((size_t)(b_*(HH*WW) + h*WW + w))*CC + cc;
    float4 v = *(const float4*)src;

    float s = v.x + v.y + v.z + v.w;
    #pragma unroll
    for (int o = 16; o > 0; o >>= 1) s += __shfl_xor_sync(0xffffffffu, s, o);
    if (lane == 0) sred[warp] = s;
    __syncthreads();
    float m = (sred[0]+sred[1]+sred[2]+sred[3]) * (1.0f/512.0f);

    float dx = v.x-m, dy = v.y-m, dz = v.z-m, dwv = v.w-m;
    float q = dx*dx + dy*dy + dz*dz + dwv*dwv;
    #pragma unroll
    for (int o = 16; o > 0; o >>= 1) q += __shfl_xor_sync(0xffffffffu, q, o);
    if (lane == 0) sred[4+warp] = q;
    __syncthreads();
    float var = (sred[4]+sred[5]+sred[6]+sred[7]) * (1.0f/512.0f);
    float inv = rsqrtf(var + 1e-5f);

    int oc = tid*4;
    float4 gg = *(const float4*)(g + oc);
    float4 bb = *(const float4*)(b + oc);
    float4 r;
    r.x = dx*inv*gg.x + bb.x;
    r.y = dy*inv*gg.y + bb.y;
    r.z = dz*inv*gg.z + bb.z;
    r.w = dwv*inv*gg.w + bb.w;
    *(float4*)(out + (size_t)token*512 + oc) = r;
}

// ---------------- host orchestration ----------------
extern "C" void kernel_launch(void* const* d_in, const int* in_sizes, int n_in,
                              void* d_out, int out_size)
{
    (void)in_sizes; (void)n_in; (void)out_size;
    const float* P[28];
    for (int i = 0; i < 28; i++) P[i] = (const float*)d_in[i];
    const float* mln_g = P[25];
    const float* mln_b = P[26];
    const float* red_w = P[27];

    float *px, *pln, *pbig, *pattn, *pxc, *pwt;
    cudaGetSymbolAddress((void**)&px,   g_x);
    cudaGetSymbolAddress((void**)&pln,  g_ln);
    cudaGetSymbolAddress((void**)&pbig, g_big);
    cudaGetSymbolAddress((void**)&pattn,g_attn);
    cudaGetSymbolAddress((void**)&pxc,  g_xc);
    cudaGetSymbolAddress((void**)&pwt,  g_wt);

    static int smem_set = 0;
    if (!smem_set) {
        cudaFuncSetAttribute(tgemm<0,128,0>, cudaFuncAttributeMaxDynamicSharedMemorySize, GSMEM);
        cudaFuncSetAttribute(tgemm<1,128,1>, cudaFuncAttributeMaxDynamicSharedMemorySize, GSMEM);
        cudaFuncSetAttribute(tgemm<2,128,0>, cudaFuncAttributeMaxDynamicSharedMemorySize, GSMEM);
        cudaFuncSetAttribute(tgemm<3,512,2>, cudaFuncAttributeMaxDynamicSharedMemorySize, GSMEM);
        cudaFuncSetAttribute(tgemm<3,512,0>, cudaFuncAttributeMaxDynamicSharedMemorySize, GSMEM);
        cudaFuncSetAttribute(tgemm<4,512,0>, cudaFuncAttributeMaxDynamicSharedMemorySize, GSMEM);
        cudaFuncSetAttribute(attn_tc_kernel, cudaFuncAttributeMaxDynamicSharedMemorySize, ASMEM);
        smem_set = 1;
    }

    // ---- all weight transposes in one launch ----
    wtrans_all_kernel<<<512, 256>>>(P[3], P[5], P[9], P[11],
                                    P[15], P[17], P[21], P[23],
                                    red_w, pwt);

    // ---- block 0 (W-MSA, shift 0) ----
    ln_kernel<<<TT/8, 256>>>((const float*)d_in[0], P[1], P[2], pln, px, 0, 1);
    tgemm<0,128,0><<<dim3(3, TT/128), 256, GSMEM>>>(pln, pwt, P[4], pbig, nullptr, nullptr, nullptr, nullptr, TT, 384, 0);
    attn_tc_kernel<<<WTOT, 256, ASMEM>>>(pbig, pattn, 0);
    tgemm<1,128,1><<<dim3(1, TT/128), 256, GSMEM>>>(pattn, pwt+49152, P[6], px, px, P[7], P[8], pln, TT, 128, 0);
    tgemm<2,128,0><<<dim3(4, TT/128), 256, GSMEM>>>(pln, pwt+65536, P[10], pbig, nullptr, nullptr, nullptr, nullptr, TT, 512, 0);
    tgemm<3,512,2><<<dim3(1, TT/128), 256, GSMEM>>>(pbig, pwt+131072, P[12], px, px, P[13], P[14], pln, TT, 128, 4);

    // ---- block 1 (SW-MSA, shift 4) ----
    tgemm<0,128,0><<<dim3(3, TT/128), 256, GSMEM>>>(pln, pwt+196608, P[16], pbig, nullptr, nullptr, nullptr, nullptr, TT, 384, 0);
    attn_tc_kernel<<<WTOT, 256, ASMEM>>>(pbig, pattn, 1);
    tgemm<1,128,1><<<dim3(1, TT/128), 256, GSMEM>>>(pattn, pwt+196608+49152, P[18], px, px, P[19], P[20], pln, TT, 128, 4);
    tgemm<2,128,0><<<dim3(4, TT/128), 256, GSMEM>>>(pln, pwt+196608+65536, P[22], pbig, nullptr, nullptr, nullptr, nullptr, TT, 512, 0);
    tgemm<3,512,0><<<dim3(1, TT/128), 256, GSMEM>>>(pbig, pwt+196608+131072, P[24], px, px, nullptr, nullptr, nullptr, TT, 128, 0);

    merge_ln_kernel<<<TT/4, 128>>>(px, mln_g, mln_b, pxc);
    tgemm<4,512,0><<<dim3(2, (TT/4)/128), 256, GSMEM>>>(pxc, pwt+393216, nullptr, (float*)d_out, nullptr, nullptr, nullptr, nullptr, TT/4, 256, 0);
}

// round 13
// speedup vs baseline: 1.7616x; 1.0184x over previous
#include <cuda_runtime.h>
#include <cuda_bf16.h>
#include <math.h>
#include <stdint.h>

// ---------------- problem constants ----------------
#define BB   8
#define HH   96
#define WW   96
#define CC   128
#define TT   (BB*HH*WW)      // 73728 tokens
#define NWIN 144             // 12*12 windows per image
#define WTOT (BB*NWIN)       // 1152 windows
#define NTOK 64              // tokens per window

// ---------------- scratch (device globals; no allocation) ----------------
__device__ float g_x[TT*CC];
__device__ float g_ln[TT*CC];
__device__ float g_big[TT*512];
__device__ float g_attn[TT*CC];
__device__ float g_xc[(TT/4)*512];
__device__ float g_wt[524288];        // transposed weights [N][K]

// ---------------- helpers ----------------
__device__ __forceinline__ uint32_t smem_u32(const void* p) {
    uint32_t a;
    asm("{ .reg .u64 t; cvta.to.shared.u64 t, %1; cvt.u32.u64 %0, t; }" : "=r"(a) : "l"(p));
    return a;
}
__device__ __forceinline__ void cp16(uint32_t dst, const void* src) {
    asm volatile("cp.async.cg.shared.global [%0], [%1], 16;" :: "r"(dst), "l"(src));
}
__device__ __forceinline__ void cp_commit() {
    asm volatile("cp.async.commit_group;" ::: "memory");
}
template<int N>
__device__ __forceinline__ void cp_wait() {
    asm volatile("cp.async.wait_group %0;" :: "n"(N) : "memory");
}
__device__ __forceinline__ void mma_tf32(float* c, const uint32_t* a, const uint32_t* b) {
    asm volatile(
        "mma.sync.aligned.m16n8k8.row.col.f32.tf32.tf32.f32 "
        "{%0,%1,%2,%3}, {%4,%5,%6,%7}, {%8,%9}, {%0,%1,%2,%3};"
        : "+f"(c[0]), "+f"(c[1]), "+f"(c[2]), "+f"(c[3])
        : "r"(a[0]), "r"(a[1]), "r"(a[2]), "r"(a[3]), "r"(b[0]), "r"(b[1]));
}
__device__ __forceinline__ void ldsm4(uint32_t* r, uint32_t addr) {
    asm volatile("ldmatrix.sync.aligned.m8n8.x4.shared.b16 {%0,%1,%2,%3}, [%4];"
        : "=r"(r[0]), "=r"(r[1]), "=r"(r[2]), "=r"(r[3]) : "r"(addr));
}
__device__ __forceinline__ uint32_t cvt_tf32f(float x) {
    uint32_t y;
    asm("cvt.rna.tf32.f32 %0, %1;" : "=r"(y) : "f"(x));
    return y;
}

// window-ordered row -> natural token (reverse roll by +shift)
__device__ __forceinline__ int win_to_token(int m, int shift) {
    int b   = m / (NWIN*NTOK);
    int rem = m - b*(NWIN*NTOK);
    int win = rem >> 6;
    int n   = rem & 63;
    int wr = win / 12, wc = win - wr*12;
    int hp = wr*8 + (n >> 3);
    int wp = wc*8 + (n & 7);
    int h = hp + shift; if (h >= HH) h -= HH;
    int w = wp + shift; if (w >= WW) w -= WW;
    return b*(HH*WW) + h*WW + w;
}
// natural token -> window-ordered index
__device__ __forceinline__ int tok_to_win(int t, int shift) {
    int bi = t / (HH*WW);
    int hw = t - bi*(HH*WW);
    int h = hw / WW, w = hw - (hw/WW)*WW;
    int hp = h - shift; if (hp < 0) hp += HH;
    int wp = w - shift; if (wp < 0) wp += WW;
    return bi*(NWIN*NTOK) + ((hp>>3)*12 + (wp>>3))*NTOK + ((hp&7)*8 + (wp&7));
}

// ---------------- ALL weight transposes in one launch ----------------
__global__ void __launch_bounds__(256) wtrans_all_kernel(
    const float* __restrict__ qkv0, const float* __restrict__ proj0,
    const float* __restrict__ fc10, const float* __restrict__ fc20,
    const float* __restrict__ qkv1, const float* __restrict__ proj1,
    const float* __restrict__ fc11, const float* __restrict__ fc21,
    const float* __restrict__ red,  float* __restrict__ wt)
{
    __shared__ float t[32][33];
    int tb = blockIdx.x;
    const float* in; int K, N, ntn, off;
    if      (tb < 48)  {            in = qkv0;  K=128; N=384; ntn=12; off=0; }
    else if (tb < 64)  { tb -= 48;  in = proj0; K=128; N=128; ntn=4;  off=49152; }
    else if (tb < 128) { tb -= 64;  in = fc10;  K=128; N=512; ntn=16; off=65536; }
    else if (tb < 192) { tb -= 128; in = fc20;  K=512; N=128; ntn=4;  off=131072; }
    else if (tb < 240) { tb -= 192; in = qkv1;  K=128; N=384; ntn=12; off=196608; }
    else if (tb < 256) { tb -= 240; in = proj1; K=128; N=128; ntn=4;  off=196608+49152; }
    else if (tb < 320) { tb -= 256; in = fc11;  K=128; N=512; ntn=16; off=196608+65536; }
    else if (tb < 384) { tb -= 320; in = fc21;  K=512; N=128; ntn=4;  off=196608+131072; }
    else               { tb -= 384; in = red;   K=512; N=256; ntn=8;  off=393216; }
    int n0 = (tb % ntn)*32, k0 = (tb / ntn)*32;
    float* outp = wt + off;
    int x = threadIdx.x & 31, y = threadIdx.x >> 5;
    #pragma unroll
    for (int i = y; i < 32; i += 8)
        t[i][x] = in[(size_t)(k0+i)*N + n0 + x];
    __syncthreads();
    #pragma unroll
    for (int i = y; i < 32; i += 8)
        outp[(size_t)(n0+i)*K + k0 + x] = t[x][i];
}

// ---------------- LN (warp per token), optional roll+window gather + raw copy ----------------
__global__ void __launch_bounds__(256) ln_kernel(
    const float* __restrict__ x, const float* __restrict__ g,
    const float* __restrict__ b, float* __restrict__ out,
    float* __restrict__ xcopy, int shift, int windowed)
{
    int warp = threadIdx.x >> 5;
    int lane = threadIdx.x & 31;
    int token = blockIdx.x*8 + warp;
    const float4* row = (const float4*)(x + (size_t)token*CC);
    float4 v = row[lane];
    if (xcopy) ((float4*)(xcopy + (size_t)token*CC))[lane] = v;
    float s = v.x + v.y + v.z + v.w;
    #pragma unroll
    for (int o = 16; o > 0; o >>= 1) s += __shfl_xor_sync(0xffffffffu, s, o);
    float m = s * (1.0f/128.0f);
    float dx = v.x - m, dy = v.y - m, dz = v.z - m, dw = v.w - m;
    float q = dx*dx + dy*dy + dz*dz + dw*dw;
    #pragma unroll
    for (int o = 16; o > 0; o >>= 1) q += __shfl_xor_sync(0xffffffffu, q, o);
    float inv = rsqrtf(q * (1.0f/128.0f) + 1e-5f);
    float4 gg = ((const float4*)g)[lane];
    float4 bb = ((const float4*)b)[lane];
    float4 r;
    r.x = dx*inv*gg.x + bb.x;
    r.y = dy*inv*gg.y + bb.y;
    r.z = dz*inv*gg.z + bb.z;
    r.w = dw*inv*gg.w + bb.w;
    int dest = token;
    if (windowed) dest = tok_to_win(token, shift);
    ((float4*)(out + (size_t)dest*CC))[lane] = r;
}

// ---------------- mma.sync tf32 GEMM, BOTH operands via ldmatrix ----------------
#define GBM 128
#define GBN 128
#define GBK 32
#define AFLT (GBM*32)
#define STAGEF (2*AFLT)
#define STAGEB (STAGEF*4)
#define NSTAGE 3
#define GSMEM (NSTAGE*STAGEB)

template<int MODE, int K, int LNF>
__global__ void __launch_bounds__(256, 2) tgemm(
    const float* __restrict__ A, const float* __restrict__ BT,
    const float* __restrict__ bias, float* __restrict__ out,
    const float* __restrict__ res,
    const float* __restrict__ lng, const float* __restrict__ lnb,
    float* __restrict__ lnout,
    int M, int N, int shift)
{
    extern __shared__ float sm[];
    uint32_t sb = smem_u32(sm);
    int tid = threadIdx.x;
    int wid = tid >> 5;
    int lane = tid & 31;
    int g = lane >> 2, q = lane & 3;
    int warp_m = wid >> 2, warp_n = wid & 3;
    int m0 = blockIdx.y * GBM, n0 = blockIdx.x * GBN;

    const float* Ab = A + (size_t)m0 * K;
    const float* Bb = BT + (size_t)n0 * K;

    int arow = tid >> 3;
    int achk = tid & 7;

    int rowlane = lane & 15;
    int hiBit = lane >> 4;
    int lo7 = lane & 7;

    float c[4][4][4];
    #pragma unroll
    for (int mt = 0; mt < 4; mt++)
        #pragma unroll
        for (int nt = 0; nt < 4; nt++)
            #pragma unroll
            for (int i = 0; i < 4; i++) c[mt][nt][i] = 0.0f;

    const int NC = K / GBK;

    auto load_tile = [&](int kb, int buf) {
        uint32_t sA = sb + buf*STAGEB;
        uint32_t sB = sA + AFLT*4;
        const float* Ap = Ab + kb*GBK;
        const float* Bp = Bb + kb*GBK;
        #pragma unroll
        for (int i = 0; i < 4; i++) {
            int r = arow + i*32;
            uint32_t off = (uint32_t)(r*8 + (achk ^ (r & 7)))*16;
            cp16(sA + off, Ap + (size_t)r*K + achk*4);
            cp16(sB + off, Bp + (size_t)r*K + achk*4);
        }
        cp_commit();
    };

    load_tile(0, 0);
    if (NC > 1) load_tile(1, 1);

    int buf = 0;
    #pragma unroll 2
    for (int kb = 0; kb < NC; kb++) {
        if (kb == NC - 1) cp_wait<0>(); else cp_wait<NSTAGE-2>();
        __syncthreads();

        if (kb + 2 < NC) {
            int nbuf = buf + 2; if (nbuf >= NSTAGE) nbuf -= NSTAGE;
            load_tile(kb + 2, nbuf);
        }

        uint32_t aBase = sb + buf*STAGEB + (uint32_t)(warp_m*64 + rowlane)*128;
        uint32_t bBase = sb + buf*STAGEB + AFLT*4 + (uint32_t)(warp_n*32 + rowlane)*128;

        #pragma unroll
        for (int ks = 0; ks < 4; ks++) {
            uint32_t physOff = ((uint32_t)((ks*2 + hiBit) ^ lo7)) << 4;
            uint32_t a[4][4], b[4][2];
            #pragma unroll
            for (int mt = 0; mt < 4; mt++)
                ldsm4(a[mt], aBase + (uint32_t)mt*2048 + physOff);
            #pragma unroll
            for (int ntp = 0; ntp < 2; ntp++) {
                uint32_t bb[4];
                ldsm4(bb, bBase + (uint32_t)ntp*2048 + physOff);
                b[2*ntp+0][0] = bb[0];
                b[2*ntp+1][0] = bb[1];
                b[2*ntp+0][1] = bb[2];
                b[2*ntp+1][1] = bb[3];
            }
            #pragma unroll
            for (int mt = 0; mt < 4; mt++)
                #pragma unroll
                for (int nt = 0; nt < 4; nt++)
                    mma_tf32(c[mt][nt], a[mt], b[nt]);
        }
        buf++; if (buf >= NSTAGE) buf = 0;
    }

    if (LNF == 0) {
        float qscale = (MODE == 0 && n0 == 0) ? 0.17677669529663687f : 1.0f;
        #pragma unroll
        for (int mt = 0; mt < 4; mt++) {
            int r0 = m0 + warp_m*64 + mt*16 + g;
            int r1 = r0 + 8;
            int t0 = r0, t1 = r1;
            if (MODE == 1) { t0 = win_to_token(r0, shift); t1 = win_to_token(r1, shift); }
            #pragma unroll
            for (int nt = 0; nt < 4; nt++) {
                int cb = n0 + warp_n*32 + nt*8 + 2*q;
                float bx = 0.f, by = 0.f;
                if (MODE != 4) { float2 bv = *(const float2*)(bias + cb); bx = bv.x; by = bv.y; }
                float v0 = c[mt][nt][0] + bx, v1 = c[mt][nt][1] + by;
                float v2 = c[mt][nt][2] + bx, v3 = c[mt][nt][3] + by;
                if (MODE == 0) {
                    v0 = __uint_as_float(cvt_tf32f(v0*qscale));
                    v1 = __uint_as_float(cvt_tf32f(v1*qscale));
                    v2 = __uint_as_float(cvt_tf32f(v2*qscale));
                    v3 = __uint_as_float(cvt_tf32f(v3*qscale));
                    float2 o0 = {v0, v1}, o1 = {v2, v3};
                    *(float2*)(out + (size_t)r0*N + cb) = o0;
                    *(float2*)(out + (size_t)r1*N + cb) = o1;
                } else if (MODE == 1) {
                    float2 rv0 = *(const float2*)(res + (size_t)t0*CC + cb);
                    float2 rv1 = *(const float2*)(res + (size_t)t1*CC + cb);
                    float2 o0 = {v0+rv0.x, v1+rv0.y}, o1 = {v2+rv1.x, v3+rv1.y};
                    *(float2*)(out + (size_t)t0*CC + cb) = o0;
                    *(float2*)(out + (size_t)t1*CC + cb) = o1;
                } else if (MODE == 2) {
                    float2 o0, o1;
                    o0.x = 0.5f*v0*(1.0f + erff(v0*0.7071067811865476f));
                    o0.y = 0.5f*v1*(1.0f + erff(v1*0.7071067811865476f));
                    o1.x = 0.5f*v2*(1.0f + erff(v2*0.7071067811865476f));
                    o1.y = 0.5f*v3*(1.0f + erff(v3*0.7071067811865476f));
                    *(float2*)(out + (size_t)r0*N + cb) = o0;
                    *(float2*)(out + (size_t)r1*N + cb) = o1;
                } else if (MODE == 3) {
                    float2 rv0 = *(const float2*)(res + (size_t)r0*N + cb);
                    float2 rv1 = *(const float2*)(res + (size_t)r1*N + cb);
                    float2 o0 = {v0+rv0.x, v1+rv0.y}, o1 = {v2+rv1.x, v3+rv1.y};
                    *(float2*)(out + (size_t)r0*N + cb) = o0;
                    *(float2*)(out + (size_t)r1*N + cb) = o1;
                } else {
                    float2 o0 = {v0, v1}, o1 = {v2, v3};
                    *(float2*)(out + (size_t)r0*N + cb) = o0;
                    *(float2*)(out + (size_t)r1*N + cb) = o1;
                }
            }
        }
    } else {
        // ---- LN-fused epilogue (MODE 1 or 3; N == 128, gridx == 1) ----
        int tok[4][2];
        float rs[4][2], rq[4][2];
        #pragma unroll
        for (int mt = 0; mt < 4; mt++) {
            int r0 = m0 + warp_m*64 + mt*16 + g;
            int r1 = r0 + 8;
            int t0 = (MODE == 1) ? win_to_token(r0, shift) : r0;
            int t1 = (MODE == 1) ? win_to_token(r1, shift) : r1;
            tok[mt][0] = t0; tok[mt][1] = t1;
            float s0 = 0.f, s1 = 0.f, q0 = 0.f, q1 = 0.f;
            #pragma unroll
            for (int nt = 0; nt < 4; nt++) {
                int cb = warp_n*32 + nt*8 + 2*q;
                float2 bv = *(const float2*)(bias + cb);
                float2 rv0 = *(const float2*)(res + (size_t)t0*CC + cb);
                float2 rv1 = *(const float2*)(res + (size_t)t1*CC + cb);
                float v0 = c[mt][nt][0] + bv.x + rv0.x;
                float v1 = c[mt][nt][1] + bv.y + rv0.y;
                float v2 = c[mt][nt][2] + bv.x + rv1.x;
                float v3 = c[mt][nt][3] + bv.y + rv1.y;
                c[mt][nt][0] = v0; c[mt][nt][1] = v1;
                c[mt][nt][2] = v2; c[mt][nt][3] = v3;
                s0 += v0 + v1; q0 += v0*v0 + v1*v1;
                s1 += v2 + v3; q1 += v2*v2 + v3*v3;
            }
            s0 += __shfl_xor_sync(0xffffffffu, s0, 1); s0 += __shfl_xor_sync(0xffffffffu, s0, 2);
            q0 += __shfl_xor_sync(0xffffffffu, q0, 1); q0 += __shfl_xor_sync(0xffffffffu, q0, 2);
            s1 += __shfl_xor_sync(0xffffffffu, s1, 1); s1 += __shfl_xor_sync(0xffffffffu, s1, 2);
            q1 += __shfl_xor_sync(0xffffffffu, q1, 1); q1 += __shfl_xor_sync(0xffffffffu, q1, 2);
            rs[mt][0] = s0; rq[mt][0] = q0;
            rs[mt][1] = s1; rq[mt][1] = q1;
        }
        __syncthreads();
        float* ps = sm;
        float* pq = sm + 512;
        if (q == 0) {
            #pragma unroll
            for (int mt = 0; mt < 4; mt++) {
                int lr0 = warp_m*64 + mt*16 + g;
                ps[warp_n*128 + lr0] = rs[mt][0];
                pq[warp_n*128 + lr0] = rq[mt][0];
                ps[warp_n*128 + lr0 + 8] = rs[mt][1];
                pq[warp_n*128 + lr0 + 8] = rq[mt][1];
            }
        }
        __syncthreads();
        #pragma unroll
        for (int mt = 0; mt < 4; mt++) {
            #pragma unroll
            for (int half = 0; half < 2; half++) {
                int lr = warp_m*64 + mt*16 + g + half*8;
                int t = tok[mt][half];
                float srow = ps[lr] + ps[128 + lr] + ps[256 + lr] + ps[384 + lr];
                float qrow = pq[lr] + pq[128 + lr] + pq[256 + lr] + pq[384 + lr];
                float mean = srow * (1.0f/128.0f);
                float var = qrow * (1.0f/128.0f) - mean*mean;
                float inv = rsqrtf(var + 1e-5f);
                int dest = (LNF == 1) ? t : tok_to_win(t, shift);
                #pragma unroll
                for (int nt = 0; nt < 4; nt++) {
                    int cb = warp_n*32 + nt*8 + 2*q;
                    float v0 = c[mt][nt][half*2+0];
                    float v1 = c[mt][nt][half*2+1];
                    float2 o = {v0, v1};
                    *(float2*)(out + (size_t)t*CC + cb) = o;
                    float2 lg = *(const float2*)(lng + cb);
                    float2 lb = *(const float2*)(lnb + cb);
                    float2 l;
                    l.x = (v0 - mean)*inv*lg.x + lb.x;
                    l.y = (v1 - mean)*inv*lg.y + lb.y;
                    *(float2*)(lnout + (size_t)dest*CC + cb) = l;
                }
            }
        }
    }
}

// ---------------- tensor-core windowed attention (R10 single-phase, 3 smem tiles) ----------------
#define ALSTR 132
#define ATILE (64*ALSTR)
#define ASMEM (3*ATILE*4)       // 101376 bytes

__global__ void __launch_bounds__(256) attn_tc_kernel(
    const float* __restrict__ qkv, float* __restrict__ out, int masked)
{
    extern __shared__ float smf[];
    float* qs = smf;
    float* ks = smf + ATILE;
    float* vs = smf + 2*ATILE;

    int tid = threadIdx.x;
    int win = blockIdx.x;
    const float* base = qkv + (size_t)win*NTOK*384;

    for (int i = tid; i < 64*32; i += 256) {
        int r = i >> 5, c4 = (i & 31) * 4;
        const float* rowp = base + (size_t)r*384 + c4;
        *(float4*)(qs + r*ALSTR + c4) = *(const float4*)(rowp);
        *(float4*)(ks + r*ALSTR + c4) = *(const float4*)(rowp + 128);
        *(float4*)(vs + r*ALSTR + c4) = *(const float4*)(rowp + 256);
    }
    __syncthreads();

    int wid = tid >> 5, lane = tid & 31;
    int h = wid >> 1, mhalf = wid & 1;
    int g = lane >> 2, q = lane & 3;
    int hb = h*32;

    int wloc = win % NWIN;
    int wr = wloc / 12, wc = wloc - wr*12;
    bool needmask = masked && (wr == 11 || wc == 11);

    const float NINF = __int_as_float(0xff800000);
    float* orow = out + (size_t)win*NTOK*CC;

    #pragma unroll
    for (int mt = 0; mt < 2; mt++) {
        int rowbase = mhalf*32 + mt*16;
        uint32_t qa[4][4];
        #pragma unroll
        for (int kc = 0; kc < 4; kc++) {
            int off = (rowbase + g)*ALSTR + hb + kc*8 + q;
            qa[kc][0] = __float_as_uint(qs[off]);
            qa[kc][1] = __float_as_uint(qs[off + 8*ALSTR]);
            qa[kc][2] = __float_as_uint(qs[off + 4]);
            qa[kc][3] = __float_as_uint(qs[off + 8*ALSTR + 4]);
        }
        float s[8][4];
        #pragma unroll
        for (int nt = 0; nt < 8; nt++) {
            s[nt][0] = s[nt][1] = s[nt][2] = s[nt][3] = 0.f;
            #pragma unroll
            for (int kc = 0; kc < 4; kc++) {
                int koff = (nt*8 + g)*ALSTR + hb + kc*8 + q;
                uint32_t b[2];
                b[0] = __float_as_uint(ks[koff]);
                b[1] = __float_as_uint(ks[koff + 4]);
                mma_tf32(s[nt], qa[kc], b);
            }
        }
        if (needmask) {
            int t0 = rowbase + g, t1 = t0 + 8;
            int lr0 = ((wr == 11) ? (((t0 >> 3) < 4) ? 1 : 2) : 0)*3 + ((wc == 11) ? (((t0 & 7) < 4) ? 1 : 2) : 0);
            int lr1 = ((wr == 11) ? (((t1 >> 3) < 4) ? 1 : 2) : 0)*3 + ((wc == 11) ? (((t1 & 7) < 4) ? 1 : 2) : 0);
            #pragma unroll
            for (int nt = 0; nt < 8; nt++) {
                int ca = nt*8 + 2*q, cb2 = ca + 1;
                int lca = ((wr == 11) ? ((nt < 4) ? 1 : 2) : 0)*3 + ((wc == 11) ? (((ca & 7) < 4) ? 1 : 2) : 0);
                int lcb = ((wr == 11) ? ((nt < 4) ? 1 : 2) : 0)*3 + ((wc == 11) ? (((cb2 & 7) < 4) ? 1 : 2) : 0);
                if (lca != lr0) s[nt][0] = NINF;
                if (lcb != lr0) s[nt][1] = NINF;
                if (lca != lr1) s[nt][2] = NINF;
                if (lcb != lr1) s[nt][3] = NINF;
            }
        }
        float mx0 = NINF, mx1 = NINF;
        #pragma unroll
        for (int nt = 0; nt < 8; nt++) {
            mx0 = fmaxf(mx0, fmaxf(s[nt][0], s[nt][1]));
            mx1 = fmaxf(mx1, fmaxf(s[nt][2], s[nt][3]));
        }
        mx0 = fmaxf(mx0, __shfl_xor_sync(0xffffffffu, mx0, 1));
        mx0 = fmaxf(mx0, __shfl_xor_sync(0xffffffffu, mx0, 2));
        mx1 = fmaxf(mx1, __shfl_xor_sync(0xffffffffu, mx1, 1));
        mx1 = fmaxf(mx1, __shfl_xor_sync(0xffffffffu, mx1, 2));
        float sum0 = 0.f, sum1 = 0.f;
        #pragma unroll
        for (int nt = 0; nt < 8; nt++) {
            s[nt][0] = __expf(s[nt][0] - mx0);
            s[nt][1] = __expf(s[nt][1] - mx0);
            s[nt][2] = __expf(s[nt][2] - mx1);
            s[nt][3] = __expf(s[nt][3] - mx1);
            sum0 += s[nt][0] + s[nt][1];
            sum1 += s[nt][2] + s[nt][3];
        }
        sum0 += __shfl_xor_sync(0xffffffffu, sum0, 1);
        sum0 += __shfl_xor_sync(0xffffffffu, sum0, 2);
        sum1 += __shfl_xor_sync(0xffffffffu, sum1, 1);
        sum1 += __shfl_xor_sync(0xffffffffu, sum1, 2);
        float inv0 = 1.0f / sum0, inv1 = 1.0f / sum1;

        float o[4][4];
        #pragma unroll
        for (int nt = 0; nt < 4; nt++) { o[nt][0]=o[nt][1]=o[nt][2]=o[nt][3]=0.f; }
        int sl = (g << 2) + (q >> 1);
        bool odd = (q & 1);
        #pragma unroll
        for (int kc = 0; kc < 8; kc++) {
            float x0 = __shfl_sync(0xffffffffu, s[kc][0], sl);
            float x1 = __shfl_sync(0xffffffffu, s[kc][1], sl);
            float y0 = __shfl_sync(0xffffffffu, s[kc][2], sl);
            float y1 = __shfl_sync(0xffffffffu, s[kc][3], sl);
            float x2 = __shfl_sync(0xffffffffu, s[kc][0], sl + 2);
            float x3 = __shfl_sync(0xffffffffu, s[kc][1], sl + 2);
            float y2 = __shfl_sync(0xffffffffu, s[kc][2], sl + 2);
            float y3 = __shfl_sync(0xffffffffu, s[kc][3], sl + 2);
            uint32_t pa[4];
            pa[0] = cvt_tf32f(odd ? x1 : x0);
            pa[1] = cvt_tf32f(odd ? y1 : y0);
            pa[2] = cvt_tf32f(odd ? x3 : x2);
            pa[3] = cvt_tf32f(odd ? y3 : y2);
            #pragma unroll
            for (int nt = 0; nt < 4; nt++) {
                int voff0 = (kc*8 + q)*ALSTR + hb + nt*8 + g;
                int voff1 = (kc*8 + q + 4)*ALSTR + hb + nt*8 + g;
                uint32_t b[2];
                b[0] = __float_as_uint(vs[voff0]);
                b[1] = __float_as_uint(vs[voff1]);
                mma_tf32(o[nt], pa, b);
            }
        }
        #pragma unroll
        for (int nt = 0; nt < 4; nt++) {
            int col = hb + nt*8 + 2*q;
            float2 o0 = {o[nt][0]*inv0, o[nt][1]*inv0};
            float2 o1 = {o[nt][2]*inv1, o[nt][3]*inv1};
            *(float2*)(orow + (size_t)(rowbase + g)*CC + col) = o0;
            *(float2*)(orow + (size_t)(rowbase + g + 8)*CC + col) = o1;
        }
    }
}

// ---------------- patch-merge gather + LN over 512 ----------------
__global__ void __launch_bounds__(128) merge_ln_kernel(
    const float* __restrict__ x, const float* __restrict__ g,
    const float* __restrict__ b, float* __restrict__ out)
{
    __shared__ float sred[8];
    int token = blockIdx.x;
    int b_ = token / 2304;
    int ij = token - b_*2304;
    int i2 = ij / 48, j2 = ij - (ij/48)*48;
    int tid = threadIdx.x;
    int warp = tid >> 5, lane = tid & 31;
    int chunk = tid >> 5;
    int cc = (tid & 31) * 4;
    int dh = chunk & 1, dw = chunk >> 1;
    int h = 2*i2 + dh, w = 2*j2 + dw;
    const float* src = x + ((size_t)(b_*(HH*WW) + h*WW + w))*CC + cc;
    float4 v = *(const float4*)src;

    float s = v.x + v.y + v.z + v.w;
    #pragma unroll
    for (int o = 16; o > 0; o >>= 1) s += __shfl_xor_sync(0xffffffffu, s, o);
    if (lane == 0) sred[warp] = s;
    __syncthreads();
    float m = (sred[0]+sred[1]+sred[2]+sred[3]) * (1.0f/512.0f);

    float dx = v.x-m, dy = v.y-m, dz = v.z-m, dwv = v.w-m;
    float q = dx*dx + dy*dy + dz*dz + dwv*dwv;
    #pragma unroll
    for (int o = 16; o > 0; o >>= 1) q += __shfl_xor_sync(0xffffffffu, q, o);
    if (lane == 0) sred[4+warp] = q;
    __syncthreads();
    float var = (sred[4]+sred[5]+sred[6]+sred[7]) * (1.0f/512.0f);
    float inv = rsqrtf(var + 1e-5f);

    int oc = tid*4;
    float4 gg = *(const float4*)(g + oc);
    float4 bb = *(const float4*)(b + oc);
    float4 r;
    r.x = dx*inv*gg.x + bb.x;
    r.y = dy*inv*gg.y + bb.y;
    r.z = dz*inv*gg.z + bb.z;
    r.w = dwv*inv*gg.w + bb.w;
    *(float4*)(out + (size_t)token*512 + oc) = r;
}

// ---------------- host orchestration ----------------
extern "C" void kernel_launch(void* const* d_in, const int* in_sizes, int n_in,
                              void* d_out, int out_size)
{
    (void)in_sizes; (void)n_in; (void)out_size;
    const float* P[28];
    for (int i = 0; i < 28; i++) P[i] = (const float*)d_in[i];
    const float* mln_g = P[25];
    const float* mln_b = P[26];
    const float* red_w = P[27];

    float *px, *pln, *pbig, *pattn, *pxc, *pwt;
    cudaGetSymbolAddress((void**)&px,   g_x);
    cudaGetSymbolAddress((void**)&pln,  g_ln);
    cudaGetSymbolAddress((void**)&pbig, g_big);
    cudaGetSymbolAddress((void**)&pattn,g_attn);
    cudaGetSymbolAddress((void**)&pxc,  g_xc);
    cudaGetSymbolAddress((void**)&pwt,  g_wt);

    static int smem_set = 0;
    if (!smem_set) {
        cudaFuncSetAttribute(tgemm<0,128,0>, cudaFuncAttributeMaxDynamicSharedMemorySize, GSMEM);
        cudaFuncSetAttribute(tgemm<1,128,1>, cudaFuncAttributeMaxDynamicSharedMemorySize, GSMEM);
        cudaFuncSetAttribute(tgemm<2,128,0>, cudaFuncAttributeMaxDynamicSharedMemorySize, GSMEM);
        cudaFuncSetAttribute(tgemm<3,512,2>, cudaFuncAttributeMaxDynamicSharedMemorySize, GSMEM);
        cudaFuncSetAttribute(tgemm<3,512,0>, cudaFuncAttributeMaxDynamicSharedMemorySize, GSMEM);
        cudaFuncSetAttribute(tgemm<4,512,0>, cudaFuncAttributeMaxDynamicSharedMemorySize, GSMEM);
        cudaFuncSetAttribute(attn_tc_kernel, cudaFuncAttributeMaxDynamicSharedMemorySize, ASMEM);
        smem_set = 1;
    }

    // ---- all weight transposes in one launch ----
    wtrans_all_kernel<<<512, 256>>>(P[3], P[5], P[9], P[11],
                                    P[15], P[17], P[21], P[23],
                                    red_w, pwt);

    // ---- block 0 (W-MSA, shift 0) ----
    ln_kernel<<<TT/8, 256>>>((const float*)d_in[0], P[1], P[2], pln, px, 0, 1);
    tgemm<0,128,0><<<dim3(3, TT/128), 256, GSMEM>>>(pln, pwt, P[4], pbig, nullptr, nullptr, nullptr, nullptr, TT, 384, 0);
    attn_tc_kernel<<<WTOT, 256, ASMEM>>>(pbig, pattn, 0);
    tgemm<1,128,1><<<dim3(1, TT/128), 256, GSMEM>>>(pattn, pwt+49152, P[6], px, px, P[7], P[8], pln, TT, 128, 0);
    tgemm<2,128,0><<<dim3(4, TT/128), 256, GSMEM>>>(pln, pwt+65536, P[10], pbig, nullptr, nullptr, nullptr, nullptr, TT, 512, 0);
    tgemm<3,512,2><<<dim3(1, TT/128), 256, GSMEM>>>(pbig, pwt+131072, P[12], px, px, P[13], P[14], pln, TT, 128, 4);

    // ---- block 1 (SW-MSA, shift 4) ----
    tgemm<0,128,0><<<dim3(3, TT/128), 256, GSMEM>>>(pln, pwt+196608, P[16], pbig, nullptr, nullptr, nullptr, nullptr, TT, 384, 0);
    attn_tc_kernel<<<WTOT, 256, ASMEM>>>(pbig, pattn, 1);
    tgemm<1,128,1><<<dim3(1, TT/128), 256, GSMEM>>>(pattn, pwt+196608+49152, P[18], px, px, P[19], P[20], pln, TT, 128, 4);
    tgemm<2,128,0><<<dim3(4, TT/128), 256, GSMEM>>>(pln, pwt+196608+65536, P[22], pbig, nullptr, nullptr, nullptr, nullptr, TT, 512, 0);
    tgemm<3,512,0><<<dim3(1, TT/128), 256, GSMEM>>>(pbig, pwt+196608+131072, P[24], px, px, nullptr, nullptr, nullptr, TT, 128, 0);

    merge_ln_kernel<<<TT/4, 128>>>(px, mln_g, mln_b, pxc);
    tgemm<4,512,0><<<dim3(2, (TT/4)/128), 256, GSMEM>>>(pxc, pwt+393216, nullptr, (float*)d_out, nullptr, nullptr, nullptr, nullptr, TT/4, 256, 0);
}

// round 14
// speedup vs baseline: 1.8461x; 1.0480x over previous
#include <cuda_runtime.h>
#include <cuda_bf16.h>
#include <math.h>
#include <stdint.h>

// ---------------- problem constants ----------------
#define BB   8
#define HH   96
#define WW   96
#define CC   128
#define TT   (BB*HH*WW)      // 73728 tokens
#define NWIN 144             // 12*12 windows per image
#define WTOT (BB*NWIN)       // 1152 windows
#define NTOK 64              // tokens per window

// ---------------- scratch (device globals; no allocation) ----------------
__device__ float g_x[TT*CC];
__device__ float g_ln[TT*CC];
__device__ float g_big[TT*512];
__device__ float g_attn[TT*CC];
__device__ float g_xc[(TT/4)*512];
__device__ float g_wt[524288];        // transposed weights [N][K]

// ---------------- helpers ----------------
__device__ __forceinline__ uint32_t smem_u32(const void* p) {
    uint32_t a;
    asm("{ .reg .u64 t; cvta.to.shared.u64 t, %1; cvt.u32.u64 %0, t; }" : "=r"(a) : "l"(p));
    return a;
}
__device__ __forceinline__ void cp16(uint32_t dst, const void* src) {
    asm volatile("cp.async.cg.shared.global [%0], [%1], 16;" :: "r"(dst), "l"(src));
}
__device__ __forceinline__ void cp_commit() {
    asm volatile("cp.async.commit_group;" ::: "memory");
}
template<int N>
__device__ __forceinline__ void cp_wait() {
    asm volatile("cp.async.wait_group %0;" :: "n"(N) : "memory");
}
__device__ __forceinline__ void mma_tf32(float* c, const uint32_t* a, const uint32_t* b) {
    asm volatile(
        "mma.sync.aligned.m16n8k8.row.col.f32.tf32.tf32.f32 "
        "{%0,%1,%2,%3}, {%4,%5,%6,%7}, {%8,%9}, {%0,%1,%2,%3};"
        : "+f"(c[0]), "+f"(c[1]), "+f"(c[2]), "+f"(c[3])
        : "r"(a[0]), "r"(a[1]), "r"(a[2]), "r"(a[3]), "r"(b[0]), "r"(b[1]));
}
__device__ __forceinline__ void ldsm4(uint32_t* r, uint32_t addr) {
    asm volatile("ldmatrix.sync.aligned.m8n8.x4.shared.b16 {%0,%1,%2,%3}, [%4];"
        : "=r"(r[0]), "=r"(r[1]), "=r"(r[2]), "=r"(r[3]) : "r"(addr));
}
__device__ __forceinline__ uint32_t cvt_tf32f(float x) {
    uint32_t y;
    asm("cvt.rna.tf32.f32 %0, %1;" : "=r"(y) : "f"(x));
    return y;
}

// window-ordered row -> natural token (reverse roll by +shift)
__device__ __forceinline__ int win_to_token(int m, int shift) {
    int b   = m / (NWIN*NTOK);
    int rem = m - b*(NWIN*NTOK);
    int win = rem >> 6;
    int n   = rem & 63;
    int wr = win / 12, wc = win - wr*12;
    int hp = wr*8 + (n >> 3);
    int wp = wc*8 + (n & 7);
    int h = hp + shift; if (h >= HH) h -= HH;
    int w = wp + shift; if (w >= WW) w -= WW;
    return b*(HH*WW) + h*WW + w;
}
// natural token -> window-ordered index
__device__ __forceinline__ int tok_to_win(int t, int shift) {
    int bi = t / (HH*WW);
    int hw = t - bi*(HH*WW);
    int h = hw / WW, w = hw - (hw/WW)*WW;
    int hp = h - shift; if (hp < 0) hp += HH;
    int wp = w - shift; if (wp < 0) wp += WW;
    return bi*(NWIN*NTOK) + ((hp>>3)*12 + (wp>>3))*NTOK + ((hp&7)*8 + (wp&7));
}

// ---------------- ALL weight transposes in one launch ----------------
__global__ void __launch_bounds__(256) wtrans_all_kernel(
    const float* __restrict__ qkv0, const float* __restrict__ proj0,
    const float* __restrict__ fc10, const float* __restrict__ fc20,
    const float* __restrict__ qkv1, const float* __restrict__ proj1,
    const float* __restrict__ fc11, const float* __restrict__ fc21,
    const float* __restrict__ red,  float* __restrict__ wt)
{
    __shared__ float t[32][33];
    int tb = blockIdx.x;
    const float* in; int K, N, ntn, off;
    if      (tb < 48)  {            in = qkv0;  K=128; N=384; ntn=12; off=0; }
    else if (tb < 64)  { tb -= 48;  in = proj0; K=128; N=128; ntn=4;  off=49152; }
    else if (tb < 128) { tb -= 64;  in = fc10;  K=128; N=512; ntn=16; off=65536; }
    else if (tb < 192) { tb -= 128; in = fc20;  K=512; N=128; ntn=4;  off=131072; }
    else if (tb < 240) { tb -= 192; in = qkv1;  K=128; N=384; ntn=12; off=196608; }
    else if (tb < 256) { tb -= 240; in = proj1; K=128; N=128; ntn=4;  off=196608+49152; }
    else if (tb < 320) { tb -= 256; in = fc11;  K=128; N=512; ntn=16; off=196608+65536; }
    else if (tb < 384) { tb -= 320; in = fc21;  K=512; N=128; ntn=4;  off=196608+131072; }
    else               { tb -= 384; in = red;   K=512; N=256; ntn=8;  off=393216; }
    int n0 = (tb % ntn)*32, k0 = (tb / ntn)*32;
    float* outp = wt + off;
    int x = threadIdx.x & 31, y = threadIdx.x >> 5;
    #pragma unroll
    for (int i = y; i < 32; i += 8)
        t[i][x] = in[(size_t)(k0+i)*N + n0 + x];
    __syncthreads();
    #pragma unroll
    for (int i = y; i < 32; i += 8)
        outp[(size_t)(n0+i)*K + k0 + x] = t[x][i];
}

// ---------------- LN (warp per token), optional roll+window gather + raw copy ----------------
__global__ void __launch_bounds__(256) ln_kernel(
    const float* __restrict__ x, const float* __restrict__ g,
    const float* __restrict__ b, float* __restrict__ out,
    float* __restrict__ xcopy, int shift, int windowed)
{
    int warp = threadIdx.x >> 5;
    int lane = threadIdx.x & 31;
    int token = blockIdx.x*8 + warp;
    const float4* row = (const float4*)(x + (size_t)token*CC);
    float4 v = row[lane];
    if (xcopy) ((float4*)(xcopy + (size_t)token*CC))[lane] = v;
    float s = v.x + v.y + v.z + v.w;
    #pragma unroll
    for (int o = 16; o > 0; o >>= 1) s += __shfl_xor_sync(0xffffffffu, s, o);
    float m = s * (1.0f/128.0f);
    float dx = v.x - m, dy = v.y - m, dz = v.z - m, dw = v.w - m;
    float q = dx*dx + dy*dy + dz*dz + dw*dw;
    #pragma unroll
    for (int o = 16; o > 0; o >>= 1) q += __shfl_xor_sync(0xffffffffu, q, o);
    float inv = rsqrtf(q * (1.0f/128.0f) + 1e-5f);
    float4 gg = ((const float4*)g)[lane];
    float4 bb = ((const float4*)b)[lane];
    float4 r;
    r.x = dx*inv*gg.x + bb.x;
    r.y = dy*inv*gg.y + bb.y;
    r.z = dz*inv*gg.z + bb.z;
    r.w = dw*inv*gg.w + bb.w;
    int dest = token;
    if (windowed) dest = tok_to_win(token, shift);
    ((float4*)(out + (size_t)dest*CC))[lane] = r;
}

// ---------------- mma.sync tf32 GEMM, BOTH operands via ldmatrix ----------------
#define GBM 128
#define GBN 128
#define GBK 32
#define AFLT (GBM*32)
#define STAGEF (2*AFLT)
#define STAGEB (STAGEF*4)
#define NSTAGE 3
#define GSMEM (NSTAGE*STAGEB)

template<int MODE, int K, int LNF>
__global__ void __launch_bounds__(256, 2) tgemm(
    const float* __restrict__ A, const float* __restrict__ BT,
    const float* __restrict__ bias, float* __restrict__ out,
    const float* __restrict__ res,
    const float* __restrict__ lng, const float* __restrict__ lnb,
    float* __restrict__ lnout,
    int M, int N, int shift)
{
    extern __shared__ float sm[];
    uint32_t sb = smem_u32(sm);
    int tid = threadIdx.x;
    int wid = tid >> 5;
    int lane = tid & 31;
    int g = lane >> 2, q = lane & 3;
    int warp_m = wid >> 2, warp_n = wid & 3;
    int m0 = blockIdx.y * GBM, n0 = blockIdx.x * GBN;

    const float* Ab = A + (size_t)m0 * K;
    const float* Bb = BT + (size_t)n0 * K;

    int arow = tid >> 3;
    int achk = tid & 7;

    int rowlane = lane & 15;
    int hiBit = lane >> 4;
    int lo7 = lane & 7;

    float c[4][4][4];
    #pragma unroll
    for (int mt = 0; mt < 4; mt++)
        #pragma unroll
        for (int nt = 0; nt < 4; nt++)
            #pragma unroll
            for (int i = 0; i < 4; i++) c[mt][nt][i] = 0.0f;

    const int NC = K / GBK;

    auto load_tile = [&](int kb, int buf) {
        uint32_t sA = sb + buf*STAGEB;
        uint32_t sB = sA + AFLT*4;
        const float* Ap = Ab + kb*GBK;
        const float* Bp = Bb + kb*GBK;
        #pragma unroll
        for (int i = 0; i < 4; i++) {
            int r = arow + i*32;
            uint32_t off = (uint32_t)(r*8 + (achk ^ (r & 7)))*16;
            cp16(sA + off, Ap + (size_t)r*K + achk*4);
            cp16(sB + off, Bp + (size_t)r*K + achk*4);
        }
        cp_commit();
    };

    load_tile(0, 0);
    if (NC > 1) load_tile(1, 1);

    int buf = 0;
    #pragma unroll 2
    for (int kb = 0; kb < NC; kb++) {
        if (kb == NC - 1) cp_wait<0>(); else cp_wait<NSTAGE-2>();
        __syncthreads();

        if (kb + 2 < NC) {
            int nbuf = buf + 2; if (nbuf >= NSTAGE) nbuf -= NSTAGE;
            load_tile(kb + 2, nbuf);
        }

        uint32_t aBase = sb + buf*STAGEB + (uint32_t)(warp_m*64 + rowlane)*128;
        uint32_t bBase = sb + buf*STAGEB + AFLT*4 + (uint32_t)(warp_n*32 + rowlane)*128;

        #pragma unroll
        for (int ks = 0; ks < 4; ks++) {
            uint32_t physOff = ((uint32_t)((ks*2 + hiBit) ^ lo7)) << 4;
            uint32_t a[4][4], b[4][2];
            #pragma unroll
            for (int mt = 0; mt < 4; mt++)
                ldsm4(a[mt], aBase + (uint32_t)mt*2048 + physOff);
            #pragma unroll
            for (int ntp = 0; ntp < 2; ntp++) {
                uint32_t bb[4];
                ldsm4(bb, bBase + (uint32_t)ntp*2048 + physOff);
                b[2*ntp+0][0] = bb[0];
                b[2*ntp+1][0] = bb[1];
                b[2*ntp+0][1] = bb[2];
                b[2*ntp+1][1] = bb[3];
            }
            #pragma unroll
            for (int mt = 0; mt < 4; mt++)
                #pragma unroll
                for (int nt = 0; nt < 4; nt++)
                    mma_tf32(c[mt][nt], a[mt], b[nt]);
        }
        buf++; if (buf >= NSTAGE) buf = 0;
    }

    if (LNF == 0) {
        float qscale = (MODE == 0 && n0 == 0) ? 0.17677669529663687f : 1.0f;
        #pragma unroll
        for (int mt = 0; mt < 4; mt++) {
            int r0 = m0 + warp_m*64 + mt*16 + g;
            int r1 = r0 + 8;
            int t0 = r0, t1 = r1;
            if (MODE == 1) { t0 = win_to_token(r0, shift); t1 = win_to_token(r1, shift); }
            #pragma unroll
            for (int nt = 0; nt < 4; nt++) {
                int cb = n0 + warp_n*32 + nt*8 + 2*q;
                float bx = 0.f, by = 0.f;
                if (MODE != 4) { float2 bv = *(const float2*)(bias + cb); bx = bv.x; by = bv.y; }
                float v0 = c[mt][nt][0] + bx, v1 = c[mt][nt][1] + by;
                float v2 = c[mt][nt][2] + bx, v3 = c[mt][nt][3] + by;
                if (MODE == 0) {
                    v0 = __uint_as_float(cvt_tf32f(v0*qscale));
                    v1 = __uint_as_float(cvt_tf32f(v1*qscale));
                    v2 = __uint_as_float(cvt_tf32f(v2*qscale));
                    v3 = __uint_as_float(cvt_tf32f(v3*qscale));
                    float2 o0 = {v0, v1}, o1 = {v2, v3};
                    *(float2*)(out + (size_t)r0*N + cb) = o0;
                    *(float2*)(out + (size_t)r1*N + cb) = o1;
                } else if (MODE == 1) {
                    float2 rv0 = *(const float2*)(res + (size_t)t0*CC + cb);
                    float2 rv1 = *(const float2*)(res + (size_t)t1*CC + cb);
                    float2 o0 = {v0+rv0.x, v1+rv0.y}, o1 = {v2+rv1.x, v3+rv1.y};
                    *(float2*)(out + (size_t)t0*CC + cb) = o0;
                    *(float2*)(out + (size_t)t1*CC + cb) = o1;
                } else if (MODE == 2) {
                    float2 o0, o1;
                    o0.x = 0.5f*v0*(1.0f + erff(v0*0.7071067811865476f));
                    o0.y = 0.5f*v1*(1.0f + erff(v1*0.7071067811865476f));
                    o1.x = 0.5f*v2*(1.0f + erff(v2*0.7071067811865476f));
                    o1.y = 0.5f*v3*(1.0f + erff(v3*0.7071067811865476f));
                    *(float2*)(out + (size_t)r0*N + cb) = o0;
                    *(float2*)(out + (size_t)r1*N + cb) = o1;
                } else if (MODE == 3) {
                    float2 rv0 = *(const float2*)(res + (size_t)r0*N + cb);
                    float2 rv1 = *(const float2*)(res + (size_t)r1*N + cb);
                    float2 o0 = {v0+rv0.x, v1+rv0.y}, o1 = {v2+rv1.x, v3+rv1.y};
                    *(float2*)(out + (size_t)r0*N + cb) = o0;
                    *(float2*)(out + (size_t)r1*N + cb) = o1;
                } else {
                    float2 o0 = {v0, v1}, o1 = {v2, v3};
                    *(float2*)(out + (size_t)r0*N + cb) = o0;
                    *(float2*)(out + (size_t)r1*N + cb) = o1;
                }
            }
        }
    } else {
        // ---- LN-fused epilogue (MODE 1 or 3; N == 128, gridx == 1) ----
        int tok[4][2];
        float rs[4][2], rq[4][2];
        #pragma unroll
        for (int mt = 0; mt < 4; mt++) {
            int r0 = m0 + warp_m*64 + mt*16 + g;
            int r1 = r0 + 8;
            int t0 = (MODE == 1) ? win_to_token(r0, shift) : r0;
            int t1 = (MODE == 1) ? win_to_token(r1, shift) : r1;
            tok[mt][0] = t0; tok[mt][1] = t1;
            float s0 = 0.f, s1 = 0.f, q0 = 0.f, q1 = 0.f;
            #pragma unroll
            for (int nt = 0; nt < 4; nt++) {
                int cb = warp_n*32 + nt*8 + 2*q;
                float2 bv = *(const float2*)(bias + cb);
                float2 rv0 = *(const float2*)(res + (size_t)t0*CC + cb);
                float2 rv1 = *(const float2*)(res + (size_t)t1*CC + cb);
                float v0 = c[mt][nt][0] + bv.x + rv0.x;
                float v1 = c[mt][nt][1] + bv.y + rv0.y;
                float v2 = c[mt][nt][2] + bv.x + rv1.x;
                float v3 = c[mt][nt][3] + bv.y + rv1.y;
                c[mt][nt][0] = v0; c[mt][nt][1] = v1;
                c[mt][nt][2] = v2; c[mt][nt][3] = v3;
                s0 += v0 + v1; q0 += v0*v0 + v1*v1;
                s1 += v2 + v3; q1 += v2*v2 + v3*v3;
            }
            s0 += __shfl_xor_sync(0xffffffffu, s0, 1); s0 += __shfl_xor_sync(0xffffffffu, s0, 2);
            q0 += __shfl_xor_sync(0xffffffffu, q0, 1); q0 += __shfl_xor_sync(0xffffffffu, q0, 2);
            s1 += __shfl_xor_sync(0xffffffffu, s1, 1); s1 += __shfl_xor_sync(0xffffffffu, s1, 2);
            q1 += __shfl_xor_sync(0xffffffffu, q1, 1); q1 += __shfl_xor_sync(0xffffffffu, q1, 2);
            rs[mt][0] = s0; rq[mt][0] = q0;
            rs[mt][1] = s1; rq[mt][1] = q1;
        }
        __syncthreads();
        float* ps = sm;
        float* pq = sm + 512;
        if (q == 0) {
            #pragma unroll
            for (int mt = 0; mt < 4; mt++) {
                int lr0 = warp_m*64 + mt*16 + g;
                ps[warp_n*128 + lr0] = rs[mt][0];
                pq[warp_n*128 + lr0] = rq[mt][0];
                ps[warp_n*128 + lr0 + 8] = rs[mt][1];
                pq[warp_n*128 + lr0 + 8] = rq[mt][1];
            }
        }
        __syncthreads();
        #pragma unroll
        for (int mt = 0; mt < 4; mt++) {
            #pragma unroll
            for (int half = 0; half < 2; half++) {
                int lr = warp_m*64 + mt*16 + g + half*8;
                int t = tok[mt][half];
                float srow = ps[lr] + ps[128 + lr] + ps[256 + lr] + ps[384 + lr];
                float qrow = pq[lr] + pq[128 + lr] + pq[256 + lr] + pq[384 + lr];
                float mean = srow * (1.0f/128.0f);
                float var = qrow * (1.0f/128.0f) - mean*mean;
                float inv = rsqrtf(var + 1e-5f);
                int dest = (LNF == 1) ? t : tok_to_win(t, shift);
                #pragma unroll
                for (int nt = 0; nt < 4; nt++) {
                    int cb = warp_n*32 + nt*8 + 2*q;
                    float v0 = c[mt][nt][half*2+0];
                    float v1 = c[mt][nt][half*2+1];
                    float2 o = {v0, v1};
                    *(float2*)(out + (size_t)t*CC + cb) = o;
                    float2 lg = *(const float2*)(lng + cb);
                    float2 lb = *(const float2*)(lnb + cb);
                    float2 l;
                    l.x = (v0 - mean)*inv*lg.x + lb.x;
                    l.y = (v1 - mean)*inv*lg.y + lb.y;
                    *(float2*)(lnout + (size_t)dest*CC + cb) = l;
                }
            }
        }
    }
}

// ---------------- tensor-core windowed attention (cp.async staging) ----------------
#define ALSTR 132
#define ATILE (64*ALSTR)
#define ASMEM (3*ATILE*4)       // 101376 bytes

__global__ void __launch_bounds__(256) attn_tc_kernel(
    const float* __restrict__ qkv, float* __restrict__ out, int masked)
{
    extern __shared__ float smf[];
    float* qs = smf;
    float* ks = smf + ATILE;
    float* vs = smf + 2*ATILE;
    uint32_t sqs = smem_u32(qs);
    uint32_t sks = smem_u32(ks);
    uint32_t svs = smem_u32(vs);

    int tid = threadIdx.x;
    int win = blockIdx.x;
    const float* base = qkv + (size_t)win*NTOK*384;

    // async staging: 64 rows x 32 float4 each of Q,K,V (24 cp16 per thread, pipelined)
    #pragma unroll
    for (int it = 0; it < 8; it++) {
        int i = tid + it*256;
        int r = i >> 5, c4 = (i & 31) * 4;
        const float* rowp = base + (size_t)r*384 + c4;
        uint32_t doff = (uint32_t)(r*ALSTR + c4)*4;
        cp16(sqs + doff, rowp);
        cp16(sks + doff, rowp + 128);
        cp16(svs + doff, rowp + 256);
    }
    cp_commit();
    cp_wait<0>();
    __syncthreads();

    int wid = tid >> 5, lane = tid & 31;
    int h = wid >> 1, mhalf = wid & 1;
    int g = lane >> 2, q = lane & 3;
    int hb = h*32;

    int wloc = win % NWIN;
    int wr = wloc / 12, wc = wloc - wr*12;
    bool needmask = masked && (wr == 11 || wc == 11);

    const float NINF = __int_as_float(0xff800000);
    float* orow = out + (size_t)win*NTOK*CC;

    #pragma unroll
    for (int mt = 0; mt < 2; mt++) {
        int rowbase = mhalf*32 + mt*16;
        uint32_t qa[4][4];
        #pragma unroll
        for (int kc = 0; kc < 4; kc++) {
            int off = (rowbase + g)*ALSTR + hb + kc*8 + q;
            qa[kc][0] = __float_as_uint(qs[off]);
            qa[kc][1] = __float_as_uint(qs[off + 8*ALSTR]);
            qa[kc][2] = __float_as_uint(qs[off + 4]);
            qa[kc][3] = __float_as_uint(qs[off + 8*ALSTR + 4]);
        }
        float s[8][4];
        #pragma unroll
        for (int nt = 0; nt < 8; nt++) {
            s[nt][0] = s[nt][1] = s[nt][2] = s[nt][3] = 0.f;
            #pragma unroll
            for (int kc = 0; kc < 4; kc++) {
                int koff = (nt*8 + g)*ALSTR + hb + kc*8 + q;
                uint32_t b[2];
                b[0] = __float_as_uint(ks[koff]);
                b[1] = __float_as_uint(ks[koff + 4]);
                mma_tf32(s[nt], qa[kc], b);
            }
        }
        if (needmask) {
            int t0 = rowbase + g, t1 = t0 + 8;
            int lr0 = ((wr == 11) ? (((t0 >> 3) < 4) ? 1 : 2) : 0)*3 + ((wc == 11) ? (((t0 & 7) < 4) ? 1 : 2) : 0);
            int lr1 = ((wr == 11) ? (((t1 >> 3) < 4) ? 1 : 2) : 0)*3 + ((wc == 11) ? (((t1 & 7) < 4) ? 1 : 2) : 0);
            #pragma unroll
            for (int nt = 0; nt < 8; nt++) {
                int ca = nt*8 + 2*q, cb2 = ca + 1;
                int lca = ((wr == 11) ? ((nt < 4) ? 1 : 2) : 0)*3 + ((wc == 11) ? (((ca & 7) < 4) ? 1 : 2) : 0);
                int lcb = ((wr == 11) ? ((nt < 4) ? 1 : 2) : 0)*3 + ((wc == 11) ? (((cb2 & 7) < 4) ? 1 : 2) : 0);
                if (lca != lr0) s[nt][0] = NINF;
                if (lcb != lr0) s[nt][1] = NINF;
                if (lca != lr1) s[nt][2] = NINF;
                if (lcb != lr1) s[nt][3] = NINF;
            }
        }
        float mx0 = NINF, mx1 = NINF;
        #pragma unroll
        for (int nt = 0; nt < 8; nt++) {
            mx0 = fmaxf(mx0, fmaxf(s[nt][0], s[nt][1]));
            mx1 = fmaxf(mx1, fmaxf(s[nt][2], s[nt][3]));
        }
        mx0 = fmaxf(mx0, __shfl_xor_sync(0xffffffffu, mx0, 1));
        mx0 = fmaxf(mx0, __shfl_xor_sync(0xffffffffu, mx0, 2));
        mx1 = fmaxf(mx1, __shfl_xor_sync(0xffffffffu, mx1, 1));
        mx1 = fmaxf(mx1, __shfl_xor_sync(0xffffffffu, mx1, 2));
        float sum0 = 0.f, sum1 = 0.f;
        #pragma unroll
        for (int nt = 0; nt < 8; nt++) {
            s[nt][0] = __expf(s[nt][0] - mx0);
            s[nt][1] = __expf(s[nt][1] - mx0);
            s[nt][2] = __expf(s[nt][2] - mx1);
            s[nt][3] = __expf(s[nt][3] - mx1);
            sum0 += s[nt][0] + s[nt][1];
            sum1 += s[nt][2] + s[nt][3];
        }
        sum0 += __shfl_xor_sync(0xffffffffu, sum0, 1);
        sum0 += __shfl_xor_sync(0xffffffffu, sum0, 2);
        sum1 += __shfl_xor_sync(0xffffffffu, sum1, 1);
        sum1 += __shfl_xor_sync(0xffffffffu, sum1, 2);
        float inv0 = 1.0f / sum0, inv1 = 1.0f / sum1;

        float o[4][4];
        #pragma unroll
        for (int nt = 0; nt < 4; nt++) { o[nt][0]=o[nt][1]=o[nt][2]=o[nt][3]=0.f; }
        int sl = (g << 2) + (q >> 1);
        bool odd = (q & 1);
        #pragma unroll
        for (int kc = 0; kc < 8; kc++) {
            float x0 = __shfl_sync(0xffffffffu, s[kc][0], sl);
            float x1 = __shfl_sync(0xffffffffu, s[kc][1], sl);
            float y0 = __shfl_sync(0xffffffffu, s[kc][2], sl);
            float y1 = __shfl_sync(0xffffffffu, s[kc][3], sl);
            float x2 = __shfl_sync(0xffffffffu, s[kc][0], sl + 2);
            float x3 = __shfl_sync(0xffffffffu, s[kc][1], sl + 2);
            float y2 = __shfl_sync(0xffffffffu, s[kc][2], sl + 2);
            float y3 = __shfl_sync(0xffffffffu, s[kc][3], sl + 2);
            uint32_t pa[4];
            pa[0] = cvt_tf32f(odd ? x1 : x0);
            pa[1] = cvt_tf32f(odd ? y1 : y0);
            pa[2] = cvt_tf32f(odd ? x3 : x2);
            pa[3] = cvt_tf32f(odd ? y3 : y2);
            #pragma unroll
            for (int nt = 0; nt < 4; nt++) {
                int voff0 = (kc*8 + q)*ALSTR + hb + nt*8 + g;
                int voff1 = (kc*8 + q + 4)*ALSTR + hb + nt*8 + g;
                uint32_t b[2];
                b[0] = __float_as_uint(vs[voff0]);
                b[1] = __float_as_uint(vs[voff1]);
                mma_tf32(o[nt], pa, b);
            }
        }
        #pragma unroll
        for (int nt = 0; nt < 4; nt++) {
            int col = hb + nt*8 + 2*q;
            float2 o0 = {o[nt][0]*inv0, o[nt][1]*inv0};
            float2 o1 = {o[nt][2]*inv1, o[nt][3]*inv1};
            *(float2*)(orow + (size_t)(rowbase + g)*CC + col) = o0;
            *(float2*)(orow + (size_t)(rowbase + g + 8)*CC + col) = o1;
        }
    }
}

// ---------------- patch-merge gather + LN over 512 ----------------
__global__ void __launch_bounds__(128) merge_ln_kernel(
    const float* __restrict__ x, const float* __restrict__ g,
    const float* __restrict__ b, float* __restrict__ out)
{
    __shared__ float sred[8];
    int token = blockIdx.x;
    int b_ = token / 2304;
    int ij = token - b_*2304;
    int i2 = ij / 48, j2 = ij - (ij/48)*48;
    int tid = threadIdx.x;
    int warp = tid >> 5, lane = tid & 31;
    int chunk = tid >> 5;
    int cc = (tid & 31) * 4;
    int dh = chunk & 1, dw = chunk >> 1;
    int h = 2*i2 + dh, w = 2*j2 + dw;
    const float* src = x + ((size_t)(b_*(HH*WW) + h*WW + w))*CC + cc;
    float4 v = *(const float4*)src;

    float s = v.x + v.y + v.z + v.w;
    #pragma unroll
    for (int o = 16; o > 0; o >>= 1) s += __shfl_xor_sync(0xffffffffu, s, o);
    if (lane == 0) sred[warp] = s;
    __syncthreads();
    float m = (sred[0]+sred[1]+sred[2]+sred[3]) * (1.0f/512.0f);

    float dx = v.x-m, dy = v.y-m, dz = v.z-m, dwv = v.w-m;
    float q = dx*dx + dy*dy + dz*dz + dwv*dwv;
    #pragma unroll
    for (int o = 16; o > 0; o >>= 1) q += __shfl_xor_sync(0xffffffffu, q, o);
    if (lane == 0) sred[4+warp] = q;
    __syncthreads();
    float var = (sred[4]+sred[5]+sred[6]+sred[7]) * (1.0f/512.0f);
    float inv = rsqrtf(var + 1e-5f);

    int oc = tid*4;
    float4 gg = *(const float4*)(g + oc);
    float4 bb = *(const float4*)(b + oc);
    float4 r;
    r.x = dx*inv*gg.x + bb.x;
    r.y = dy*inv*gg.y + bb.y;
    r.z = dz*inv*gg.z + bb.z;
    r.w = dwv*inv*gg.w + bb.w;
    *(float4*)(out + (size_t)token*512 + oc) = r;
}

// ---------------- host orchestration ----------------
extern "C" void kernel_launch(void* const* d_in, const int* in_sizes, int n_in,
                              void* d_out, int out_size)
{
    (void)in_sizes; (void)n_in; (void)out_size;
    const float* P[28];
    for (int i = 0; i < 28; i++) P[i] = (const float*)d_in[i];
    const float* mln_g = P[25];
    const float* mln_b = P[26];
    const float* red_w = P[27];

    float *px, *pln, *pbig, *pattn, *pxc, *pwt;
    cudaGetSymbolAddress((void**)&px,   g_x);
    cudaGetSymbolAddress((void**)&pln,  g_ln);
    cudaGetSymbolAddress((void**)&pbig, g_big);
    cudaGetSymbolAddress((void**)&pattn,g_attn);
    cudaGetSymbolAddress((void**)&pxc,  g_xc);
    cudaGetSymbolAddress((void**)&pwt,  g_wt);

    static int smem_set = 0;
    if (!smem_set) {
        cudaFuncSetAttribute(tgemm<0,128,0>, cudaFuncAttributeMaxDynamicSharedMemorySize, GSMEM);
        cudaFuncSetAttribute(tgemm<1,128,1>, cudaFuncAttributeMaxDynamicSharedMemorySize, GSMEM);
        cudaFuncSetAttribute(tgemm<2,128,0>, cudaFuncAttributeMaxDynamicSharedMemorySize, GSMEM);
        cudaFuncSetAttribute(tgemm<3,512,2>, cudaFuncAttributeMaxDynamicSharedMemorySize, GSMEM);
        cudaFuncSetAttribute(tgemm<3,512,0>, cudaFuncAttributeMaxDynamicSharedMemorySize, GSMEM);
        cudaFuncSetAttribute(tgemm<4,512,0>, cudaFuncAttributeMaxDynamicSharedMemorySize, GSMEM);
        cudaFuncSetAttribute(attn_tc_kernel, cudaFuncAttributeMaxDynamicSharedMemorySize, ASMEM);
        smem_set = 1;
    }

    // ---- all weight transposes in one launch ----
    wtrans_all_kernel<<<512, 256>>>(P[3], P[5], P[9], P[11],
                                    P[15], P[17], P[21], P[23],
                                    red_w, pwt);

    // ---- block 0 (W-MSA, shift 0) ----
    ln_kernel<<<TT/8, 256>>>((const float*)d_in[0], P[1], P[2], pln, px, 0, 1);
    tgemm<0,128,0><<<dim3(3, TT/128), 256, GSMEM>>>(pln, pwt, P[4], pbig, nullptr, nullptr, nullptr, nullptr, TT, 384, 0);
    attn_tc_kernel<<<WTOT, 256, ASMEM>>>(pbig, pattn, 0);
    tgemm<1,128,1><<<dim3(1, TT/128), 256, GSMEM>>>(pattn, pwt+49152, P[6], px, px, P[7], P[8], pln, TT, 128, 0);
    tgemm<2,128,0><<<dim3(4, TT/128), 256, GSMEM>>>(pln, pwt+65536, P[10], pbig, nullptr, nullptr, nullptr, nullptr, TT, 512, 0);
    tgemm<3,512,2><<<dim3(1, TT/128), 256, GSMEM>>>(pbig, pwt+131072, P[12], px, px, P[13], P[14], pln, TT, 128, 4);

    // ---- block 1 (SW-MSA, shift 4) ----
    tgemm<0,128,0><<<dim3(3, TT/128), 256, GSMEM>>>(pln, pwt+196608, P[16], pbig, nullptr, nullptr, nullptr, nullptr, TT, 384, 0);
    attn_tc_kernel<<<WTOT, 256, ASMEM>>>(pbig, pattn, 1);
    tgemm<1,128,1><<<dim3(1, TT/128), 256, GSMEM>>>(pattn, pwt+196608+49152, P[18], px, px, P[19], P[20], pln, TT, 128, 4);
    tgemm<2,128,0><<<dim3(4, TT/128), 256, GSMEM>>>(pln, pwt+196608+65536, P[22], pbig, nullptr, nullptr, nullptr, nullptr, TT, 512, 0);
    tgemm<3,512,0><<<dim3(1, TT/128), 256, GSMEM>>>(pbig, pwt+196608+131072, P[24], px, px, nullptr, nullptr, nullptr, TT, 128, 0);

    merge_ln_kernel<<<TT/4, 128>>>(px, mln_g, mln_b, pxc);
    tgemm<4,512,0><<<dim3(2, (TT/4)/128), 256, GSMEM>>>(pxc, pwt+393216, nullptr, (float*)d_out, nullptr, nullptr, nullptr, nullptr, TT/4, 256, 0);
}